// round 7
// baseline (speedup 1.0000x reference)
#include <cuda_runtime.h>
#include <cuda_bf16.h>
#include <cstdint>
#include <math.h>

// Problem constants: B=2, T=2048, C=1024, H=16, D=64, M = B*T = 4096

// ---------------------------------------------------------------------------
// Scratch (allocation forbidden -> device globals)
// ---------------------------------------------------------------------------
__device__ __nv_bfloat16 g_qkvh[4096 * 3072];     // qkv hi/lo bf16
__device__ __nv_bfloat16 g_qkvl[4096 * 3072];
__device__ __nv_bfloat16 g_xh[4096 * 1024];       // x hi/lo
__device__ __nv_bfloat16 g_xl[4096 * 1024];
__device__ __nv_bfloat16 g_wah[3072 * 1024];      // w_attn^T hi/lo  [N,K]
__device__ __nv_bfloat16 g_wal[3072 * 1024];
__device__ __nv_bfloat16 g_wph[1024 * 1024];      // w_proj^T hi/lo  [N,K]
__device__ __nv_bfloat16 g_wpl[1024 * 1024];
__device__ __nv_bfloat16 g_yh[4096 * 1024];       // attention out hi/lo
__device__ __nv_bfloat16 g_yl[4096 * 1024];

// ---------------------------------------------------------------------------
// PTX helpers (plain sm_100-safe: mma.sync + cp.async + ldmatrix)
// ---------------------------------------------------------------------------
__device__ __forceinline__ uint32_t smem_to_u32(const void* p) {
    uint32_t a;
    asm("{ .reg .u64 t; cvta.to.shared.u64 t, %1; cvt.u32.u64 %0, t; }" : "=r"(a) : "l"(p));
    return a;
}

#define CP_ASYNC16(dst_u32, src_ptr) \
    asm volatile("cp.async.cg.shared.global [%0], [%1], 16;" \
                 :: "r"(dst_u32), "l"(src_ptr) : "memory")
#define CP_COMMIT() asm volatile("cp.async.commit_group;" ::: "memory")
#define CP_WAIT(n)  asm volatile("cp.async.wait_group %0;" :: "n"(n) : "memory")

#define LDSM_X4(r0, r1, r2, r3, addr) \
    asm volatile("ldmatrix.sync.aligned.m8n8.x4.shared.b16 {%0,%1,%2,%3}, [%4];" \
                 : "=r"(r0), "=r"(r1), "=r"(r2), "=r"(r3) : "r"(addr))

// mma.sync m16n8k16 row.col f32 += bf16 * bf16
#define MMA_BF16(c, a, b) \
    asm volatile("mma.sync.aligned.m16n8k16.row.col.f32.bf16.bf16.f32 " \
                 "{%0,%1,%2,%3}, {%4,%5,%6,%7}, {%8,%9}, {%0,%1,%2,%3};" \
                 : "+f"((c)[0]), "+f"((c)[1]), "+f"((c)[2]), "+f"((c)[3]) \
                 : "r"((a)[0]), "r"((a)[1]), "r"((a)[2]), "r"((a)[3]), \
                   "r"((b)[0]), "r"((b)[1]))

// fp32 pair -> (hi, lo) bf16x2 packed in u32
__device__ __forceinline__ void split2(float x, float y, uint32_t& h, uint32_t& l) {
    __nv_bfloat162 h2 = __floats2bfloat162_rn(x, y);
    __nv_bfloat162 l2 = __floats2bfloat162_rn(x - __bfloat162float(h2.x),
                                              y - __bfloat162float(h2.y));
    h = *(uint32_t*)&h2;
    l = *(uint32_t*)&l2;
}

// ---------------------------------------------------------------------------
// Pre-pass 1: elementwise fp32 -> (hi, lo) bf16 split
// ---------------------------------------------------------------------------
__global__ __launch_bounds__(256) void split_bf16_kernel(
    const float* __restrict__ in, __nv_bfloat16* __restrict__ hi,
    __nv_bfloat16* __restrict__ lo, int n4)
{
    int i = blockIdx.x * 256 + threadIdx.x;
    if (i >= n4) return;
    float4 v = ((const float4*)in)[i];
    uint32_t h0, l0, h1, l1;
    split2(v.x, v.y, h0, l0);
    split2(v.z, v.w, h1, l1);
    ((uint32_t*)hi)[i * 2 + 0] = h0;
    ((uint32_t*)hi)[i * 2 + 1] = h1;
    ((uint32_t*)lo)[i * 2 + 0] = l0;
    ((uint32_t*)lo)[i * 2 + 1] = l1;
}

// ---------------------------------------------------------------------------
// Pre-pass 2: W[K,N] fp32 -> W^T[N,K] (hi, lo) bf16. 32x32 tiles.
// ---------------------------------------------------------------------------
__global__ __launch_bounds__(256) void transpose_split_kernel(
    const float* __restrict__ W, __nv_bfloat16* __restrict__ Th,
    __nv_bfloat16* __restrict__ Tl, int K, int N)
{
    __shared__ float tile[32][33];
    const int n0 = blockIdx.x * 32;
    const int k0 = blockIdx.y * 32;
    const int tx = threadIdx.x, ty = threadIdx.y;
    #pragma unroll
    for (int j = 0; j < 4; j++) {
        int r = ty + j * 8;
        tile[r][tx] = W[(size_t)(k0 + r) * N + n0 + tx];
    }
    __syncthreads();
    #pragma unroll
    for (int j = 0; j < 4; j++) {
        int r = ty + j * 8;
        float v = tile[tx][r];
        __nv_bfloat16 h = __float2bfloat16_rn(v);
        __nv_bfloat16 l = __float2bfloat16_rn(v - __bfloat162float(h));
        Th[(size_t)(n0 + r) * K + k0 + tx] = h;
        Tl[(size_t)(n0 + r) * K + k0 + tx] = l;
    }
}

// ---------------------------------------------------------------------------
// Tensor-core GEMM, 4 warps / 64x64 warp tiles:
//   C = Ah@Wh^T + Ah@Wl^T + Al@Wh^T + bias
// CTA 128x128, K-chunk 32, cp.async double buffer, ldmatrix frags.
// ---------------------------------------------------------------------------
#define PITCH 40
#define TILE_BF16 (128 * PITCH)
#define BUF_BF16  (4 * TILE_BF16)

__global__ __launch_bounds__(128) void mma_gemm_kernel(
    const __nv_bfloat16* __restrict__ Ah, const __nv_bfloat16* __restrict__ Al,
    const __nv_bfloat16* __restrict__ Wh, const __nv_bfloat16* __restrict__ Wl,
    const float* __restrict__ bias, float* __restrict__ Cf,
    __nv_bfloat16* __restrict__ Ch, __nv_bfloat16* __restrict__ Cl,
    int M, int N, int K)
{
    extern __shared__ __align__(16) __nv_bfloat16 sm[];
    const uint32_t sbase = smem_to_u32(sm);
    const int tid = threadIdx.x;
    const int wid = tid >> 5, lane = tid & 31;
    const int wm = wid & 1;                       // 2 m-warps of 64 rows
    const int wn = wid >> 1;                      // 2 n-warps of 64 cols
    const int ra = lane >> 2;
    const int c2 = (lane & 3) * 2;
    const int m0 = blockIdx.x * 128;
    const int n0 = blockIdx.y * 128;

    // ldmatrix per-lane geometry
    const int r8 = lane & 7;
    const int s0 = (lane >> 3) & 1;
    const int s1 = (lane >> 4) & 1;
    const int rA = r8 + s0 * 8, kA = s1 * 8;
    const int rB = r8 + s1 * 8, kB = s0 * 8;

    const __nv_bfloat16* srcs[4] = {
        Ah + (size_t)m0 * K, Al + (size_t)m0 * K,
        Wh + (size_t)n0 * K, Wl + (size_t)n0 * K
    };

    float acc[4][8][4];
    #pragma unroll
    for (int mi = 0; mi < 4; mi++)
        #pragma unroll
        for (int ni = 0; ni < 8; ni++)
            #pragma unroll
            for (int q = 0; q < 4; q++) acc[mi][ni][q] = 0.f;

    const int NCH = K >> 5;

    auto issue_chunk = [&](int ch, int buf) {
        const int k0 = ch * 32;
        #pragma unroll
        for (int t = 0; t < 4; t++) {
            const __nv_bfloat16* src0 = srcs[t] + k0;
            const uint32_t dst0 = sbase + (buf * BUF_BF16 + t * TILE_BF16) * 2;
            #pragma unroll
            for (int i = 0; i < 4; i++) {
                int idx = tid + i * 128;          // 0..511
                int row = idx >> 2, seg = idx & 3;
                CP_ASYNC16(dst0 + (row * PITCH + seg * 8) * 2,
                           src0 + (size_t)row * K + seg * 8);
            }
        }
    };

    issue_chunk(0, 0);
    CP_COMMIT();

    for (int ch = 0; ch < NCH; ch++) {
        const int buf = ch & 1;
        if (ch + 1 < NCH) {
            issue_chunk(ch + 1, buf ^ 1);
            CP_COMMIT();
            CP_WAIT(1);
        } else {
            CP_WAIT(0);
        }
        __syncthreads();

        const uint32_t boff = sbase + buf * BUF_BF16 * 2;
        #pragma unroll
        for (int ks = 0; ks < 2; ks++) {
            uint32_t ah[4][4], al[4][4], bh[8][2], bl[8][2];
            #pragma unroll
            for (int mi = 0; mi < 4; mi++) {
                const int row = wm * 64 + mi * 16 + rA;
                const uint32_t adr = boff + (row * PITCH + ks * 16 + kA) * 2;
                LDSM_X4(ah[mi][0], ah[mi][1], ah[mi][2], ah[mi][3], adr);
                LDSM_X4(al[mi][0], al[mi][1], al[mi][2], al[mi][3],
                        adr + TILE_BF16 * 2);
            }
            #pragma unroll
            for (int np = 0; np < 4; np++) {
                const int row = wn * 64 + np * 16 + rB;
                const uint32_t adr = boff + 2 * TILE_BF16 * 2 +
                                     (row * PITCH + ks * 16 + kB) * 2;
                LDSM_X4(bh[2 * np][0], bh[2 * np][1],
                        bh[2 * np + 1][0], bh[2 * np + 1][1], adr);
                LDSM_X4(bl[2 * np][0], bl[2 * np][1],
                        bl[2 * np + 1][0], bl[2 * np + 1][1],
                        adr + TILE_BF16 * 2);
            }
            #pragma unroll
            for (int mi = 0; mi < 4; mi++)
                #pragma unroll
                for (int ni = 0; ni < 8; ni++) {
                    MMA_BF16(acc[mi][ni], ah[mi], bh[ni]);
                    MMA_BF16(acc[mi][ni], ah[mi], bl[ni]);
                    MMA_BF16(acc[mi][ni], al[mi], bh[ni]);
                }
        }
        __syncthreads();
    }

    // Epilogue
    #pragma unroll
    for (int ni = 0; ni < 8; ni++) {
        const int col = n0 + wn * 64 + ni * 8 + c2;
        const float bv0 = bias[col], bv1 = bias[col + 1];
        #pragma unroll
        for (int mi = 0; mi < 4; mi++) {
            const int r0 = m0 + wm * 64 + mi * 16 + ra;
            const float v00 = acc[mi][ni][0] + bv0, v01 = acc[mi][ni][1] + bv1;
            const float v10 = acc[mi][ni][2] + bv0, v11 = acc[mi][ni][3] + bv1;
            if (Ch) {
                uint32_t h0, l0, h1, l1;
                split2(v00, v01, h0, l0);
                split2(v10, v11, h1, l1);
                *(uint32_t*)(Ch + (size_t)r0 * N + col) = h0;
                *(uint32_t*)(Cl + (size_t)r0 * N + col) = l0;
                *(uint32_t*)(Ch + (size_t)(r0 + 8) * N + col) = h1;
                *(uint32_t*)(Cl + (size_t)(r0 + 8) * N + col) = l1;
            } else {
                *(float2*)(Cf + (size_t)r0 * N + col) = make_float2(v00, v01);
                *(float2*)(Cf + (size_t)(r0 + 8) * N + col) = make_float2(v10, v11);
            }
        }
    }
}

// ---------------------------------------------------------------------------
// Tensor-core causal flash attention, 4 warps / 32 q-rows per warp.
// CTA: 128 q-rows x 64-key tiles, bf16 hi/lo in gmem, ldmatrix frags.
// smem (bf16, pitch 72): Qh Ql [128][72], Kh Kl [64][72], Vth Vtl [64][72]
// ---------------------------------------------------------------------------
#define AP 72
#define QH_OFF 0
#define QL_OFF 9216
#define KH_OFF 18432
#define KL_OFF 23040
#define VTH_OFF 27648
#define VTL_OFF 32256

__global__ __launch_bounds__(128) void attn_mma_kernel(
    const __nv_bfloat16* __restrict__ qh, const __nv_bfloat16* __restrict__ ql,
    __nv_bfloat16* __restrict__ yh, __nv_bfloat16* __restrict__ yl)
{
    extern __shared__ __align__(16) __nv_bfloat16 sma[];
    const uint32_t sbase = smem_to_u32(sma);
    const int tid = threadIdx.x;
    const int wid = tid >> 5, lane = tid & 31;
    const int gr = lane >> 2;
    const int gc = lane & 3;
    const int qt = gridDim.x - 1 - blockIdx.x;    // heavy CTAs first
    const int h  = blockIdx.y;
    const int b  = blockIdx.z;
    const int wq = wid * 32;                      // warp q-row base (local)

    const int r8 = lane & 7;
    const int s0 = (lane >> 3) & 1;
    const int s1 = (lane >> 4) & 1;
    const int rA = r8 + s0 * 8, kA = s1 * 8;
    const int rB = r8 + s1 * 8, kB = s0 * 8;

    const float SSCALE = 0.125f * 1.44269504088896f;  // 1/sqrt(64)*log2(e)

    // ---- Load Q tile (128 x 64 bf16 hi/lo) ----
    {
        const size_t qrow = (size_t)(b * 2048 + qt * 128) * 3072 + h * 64;
        #pragma unroll
        for (int i = 0; i < 8; i++) {
            int f = tid + i * 128;                // 0..1023
            int r = f >> 3, seg = f & 7;
            const size_t off = qrow + (size_t)r * 3072 + seg * 8;
            *(uint4*)&sma[QH_OFF + r * AP + seg * 8] = *(const uint4*)(qh + off);
            *(uint4*)&sma[QL_OFF + r * AP + seg * 8] = *(const uint4*)(ql + off);
        }
    }

    float o[2][8][4];
    #pragma unroll
    for (int mi = 0; mi < 2; mi++)
        #pragma unroll
        for (int j = 0; j < 8; j++)
            #pragma unroll
            for (int q = 0; q < 4; q++) o[mi][j][q] = 0.f;
    float mrow[2][2] = {{-1e30f, -1e30f}, {-1e30f, -1e30f}};
    float lrow[2][2] = {{0.f, 0.f}, {0.f, 0.f}};

    const size_t kcol = (size_t)(b * 2048) * 3072 + 1024 + h * 64;
    const size_t vcol = kcol + 1024;

    const int kt_max = 2 * qt + 1;
    for (int kt = 0; kt <= kt_max; kt++) {
        // ---- Load K (natural) and V (transposed) 64x64 tiles ----
        #pragma unroll
        for (int i = 0; i < 4; i++) {
            int f = tid + i * 128;                // 0..511
            int j = f >> 3, seg = f & 7;
            const size_t off = kcol + (size_t)(kt * 64 + j) * 3072 + seg * 8;
            *(uint4*)&sma[KH_OFF + j * AP + seg * 8] = *(const uint4*)(qh + off);
            *(uint4*)&sma[KL_OFF + j * AP + seg * 8] = *(const uint4*)(ql + off);
            const size_t voff = vcol + (size_t)(kt * 64 + j) * 3072 + seg * 8;
            uint4 vvh = *(const uint4*)(qh + voff);
            uint4 vvl = *(const uint4*)(ql + voff);
            const __nv_bfloat16* ph = (const __nv_bfloat16*)&vvh;
            const __nv_bfloat16* pl = (const __nv_bfloat16*)&vvl;
            #pragma unroll
            for (int e = 0; e < 8; e++) {
                sma[VTH_OFF + (seg * 8 + e) * AP + j] = ph[e];
                sma[VTL_OFF + (seg * 8 + e) * AP + j] = pl[e];
            }
        }
        __syncthreads();

        // ---- S = Q K^T (32x64 per warp), hi/lo 3-product ----
        float s[2][8][4];
        #pragma unroll
        for (int mi = 0; mi < 2; mi++)
            #pragma unroll
            for (int j = 0; j < 8; j++)
                #pragma unroll
                for (int q = 0; q < 4; q++) s[mi][j][q] = 0.f;

        #pragma unroll
        for (int ks = 0; ks < 4; ks++) {
            uint32_t ah[2][4], al[2][4], bh[8][2], bl[8][2];
            #pragma unroll
            for (int mi = 0; mi < 2; mi++) {
                const uint32_t adr = sbase +
                    (QH_OFF + (wq + mi * 16 + rA) * AP + ks * 16 + kA) * 2;
                LDSM_X4(ah[mi][0], ah[mi][1], ah[mi][2], ah[mi][3], adr);
                LDSM_X4(al[mi][0], al[mi][1], al[mi][2], al[mi][3],
                        adr + (QL_OFF - QH_OFF) * 2);
            }
            #pragma unroll
            for (int np = 0; np < 4; np++) {
                const uint32_t adr = sbase +
                    (KH_OFF + (np * 16 + rB) * AP + ks * 16 + kB) * 2;
                LDSM_X4(bh[2 * np][0], bh[2 * np][1],
                        bh[2 * np + 1][0], bh[2 * np + 1][1], adr);
                LDSM_X4(bl[2 * np][0], bl[2 * np][1],
                        bl[2 * np + 1][0], bl[2 * np + 1][1],
                        adr + (KL_OFF - KH_OFF) * 2);
            }
            #pragma unroll
            for (int mi = 0; mi < 2; mi++)
                #pragma unroll
                for (int j = 0; j < 8; j++) {
                    MMA_BF16(s[mi][j], ah[mi], bh[j]);
                    MMA_BF16(s[mi][j], ah[mi], bl[j]);
                    MMA_BF16(s[mi][j], al[mi], bh[j]);
                }
        }

        // ---- Scale + causal mask ----
        #pragma unroll
        for (int mi = 0; mi < 2; mi++)
            #pragma unroll
            for (int j = 0; j < 8; j++)
                #pragma unroll
                for (int q = 0; q < 4; q++) s[mi][j][q] *= SSCALE;

        if (kt >= 2 * qt) {
            #pragma unroll
            for (int mi = 0; mi < 2; mi++) {
                const int row0 = qt * 128 + wq + mi * 16 + gr;
                #pragma unroll
                for (int j = 0; j < 8; j++) {
                    const int col = kt * 64 + j * 8 + 2 * gc;
                    if (col > row0)         s[mi][j][0] = -1e30f;
                    if (col + 1 > row0)     s[mi][j][1] = -1e30f;
                    if (col > row0 + 8)     s[mi][j][2] = -1e30f;
                    if (col + 1 > row0 + 8) s[mi][j][3] = -1e30f;
                }
            }
        }

        // ---- Online softmax ----
        #pragma unroll
        for (int mi = 0; mi < 2; mi++)
            #pragma unroll
            for (int i = 0; i < 2; i++) {
                const int q0i = i * 2;
                float mx = -1e30f;
                #pragma unroll
                for (int j = 0; j < 8; j++)
                    mx = fmaxf(mx, fmaxf(s[mi][j][q0i], s[mi][j][q0i + 1]));
                mx = fmaxf(mx, __shfl_xor_sync(0xffffffffu, mx, 1));
                mx = fmaxf(mx, __shfl_xor_sync(0xffffffffu, mx, 2));
                const float mnew = fmaxf(mrow[mi][i], mx);
                const float alpha = exp2f(mrow[mi][i] - mnew);
                float rsum = 0.f;
                #pragma unroll
                for (int j = 0; j < 8; j++) {
                    s[mi][j][q0i]     = exp2f(s[mi][j][q0i] - mnew);
                    s[mi][j][q0i + 1] = exp2f(s[mi][j][q0i + 1] - mnew);
                    rsum += s[mi][j][q0i] + s[mi][j][q0i + 1];
                }
                rsum += __shfl_xor_sync(0xffffffffu, rsum, 1);
                rsum += __shfl_xor_sync(0xffffffffu, rsum, 2);
                lrow[mi][i] = lrow[mi][i] * alpha + rsum;
                mrow[mi][i] = mnew;
                #pragma unroll
                for (int j = 0; j < 8; j++) {
                    o[mi][j][q0i]     *= alpha;
                    o[mi][j][q0i + 1] *= alpha;
                }
            }

        // ---- O += P V  (V frags shared across both m-frags) ----
        #pragma unroll
        for (int t = 0; t < 4; t++) {
            uint32_t bvh[8][2], bvl[8][2];
            #pragma unroll
            for (int np = 0; np < 4; np++) {
                const uint32_t adr = sbase +
                    (VTH_OFF + (np * 16 + rB) * AP + t * 16 + kB) * 2;
                LDSM_X4(bvh[2 * np][0], bvh[2 * np][1],
                        bvh[2 * np + 1][0], bvh[2 * np + 1][1], adr);
                LDSM_X4(bvl[2 * np][0], bvl[2 * np][1],
                        bvl[2 * np + 1][0], bvl[2 * np + 1][1],
                        adr + (VTL_OFF - VTH_OFF) * 2);
            }
            #pragma unroll
            for (int mi = 0; mi < 2; mi++) {
                uint32_t pha[4], pla[4];
                split2(s[mi][2 * t][0],     s[mi][2 * t][1],     pha[0], pla[0]);
                split2(s[mi][2 * t][2],     s[mi][2 * t][3],     pha[1], pla[1]);
                split2(s[mi][2 * t + 1][0], s[mi][2 * t + 1][1], pha[2], pla[2]);
                split2(s[mi][2 * t + 1][2], s[mi][2 * t + 1][3], pha[3], pla[3]);
                #pragma unroll
                for (int j = 0; j < 8; j++) {
                    MMA_BF16(o[mi][j], pha, bvh[j]);
                    MMA_BF16(o[mi][j], pha, bvl[j]);
                    MMA_BF16(o[mi][j], pla, bvh[j]);
                }
            }
        }
        __syncthreads();
    }

    // ---- Epilogue: normalize, hi/lo split, store bf16 ----
    #pragma unroll
    for (int mi = 0; mi < 2; mi++) {
        const float inv0 = 1.0f / lrow[mi][0];
        const float inv1 = 1.0f / lrow[mi][1];
        const int row0 = b * 2048 + qt * 128 + wq + mi * 16 + gr;
        #pragma unroll
        for (int j = 0; j < 8; j++) {
            const int col = h * 64 + j * 8 + 2 * gc;
            uint32_t h0, l0, h1, l1;
            split2(o[mi][j][0] * inv0, o[mi][j][1] * inv0, h0, l0);
            split2(o[mi][j][2] * inv1, o[mi][j][3] * inv1, h1, l1);
            *(uint32_t*)(yh + (size_t)row0 * 1024 + col) = h0;
            *(uint32_t*)(yl + (size_t)row0 * 1024 + col) = l0;
            *(uint32_t*)(yh + (size_t)(row0 + 8) * 1024 + col) = h1;
            *(uint32_t*)(yl + (size_t)(row0 + 8) * 1024 + col) = l1;
        }
    }
}

// ---------------------------------------------------------------------------
// Launch
// ---------------------------------------------------------------------------
extern "C" void kernel_launch(void* const* d_in, const int* in_sizes, int n_in,
                              void* d_out, int out_size)
{
    const float* x      = (const float*)d_in[0];   // [2,2048,1024]
    const float* w_attn = (const float*)d_in[1];   // [1024,3072]
    const float* b_attn = (const float*)d_in[2];   // [3072]
    const float* w_proj = (const float*)d_in[3];   // [1024,1024]
    const float* b_proj = (const float*)d_in[4];   // [1024]
    float* out = (float*)d_out;                    // [2,2048,1024]

    __nv_bfloat16 *qkvh, *qkvl, *xh, *xl, *wah, *wal, *wph, *wpl, *yh, *yl;
    cudaGetSymbolAddress((void**)&qkvh, g_qkvh);
    cudaGetSymbolAddress((void**)&qkvl, g_qkvl);
    cudaGetSymbolAddress((void**)&xh,  g_xh);
    cudaGetSymbolAddress((void**)&xl,  g_xl);
    cudaGetSymbolAddress((void**)&wah, g_wah);
    cudaGetSymbolAddress((void**)&wal, g_wal);
    cudaGetSymbolAddress((void**)&wph, g_wph);
    cudaGetSymbolAddress((void**)&wpl, g_wpl);
    cudaGetSymbolAddress((void**)&yh,  g_yh);
    cudaGetSymbolAddress((void**)&yl,  g_yl);

    cudaFuncSetAttribute(mma_gemm_kernel,
                         cudaFuncAttributeMaxDynamicSharedMemorySize, 81920);
    cudaFuncSetAttribute(attn_mma_kernel,
                         cudaFuncAttributeMaxDynamicSharedMemorySize, 73728);

    // Pre-pass: split x, transpose+split weights
    split_bf16_kernel<<<4096, 256>>>(x, xh, xl, 4096 * 1024 / 4);
    transpose_split_kernel<<<dim3(3072 / 32, 1024 / 32), dim3(32, 8)>>>(
        w_attn, wah, wal, 1024, 3072);
    transpose_split_kernel<<<dim3(1024 / 32, 1024 / 32), dim3(32, 8)>>>(
        w_proj, wph, wpl, 1024, 1024);

    // 1) qkv = x @ w_attn + b_attn  -> hi/lo bf16 directly
    mma_gemm_kernel<<<dim3(4096 / 128, 3072 / 128), 128, 81920>>>(
        xh, xl, wah, wal, b_attn, nullptr, qkvh, qkvl, 4096, 3072, 1024);

    // 2) causal attention -> yh/yl (bf16 in, bf16 out)
    attn_mma_kernel<<<dim3(2048 / 128, 16, 2), 128, 73728>>>(qkvh, qkvl, yh, yl);

    // 3) out = y @ w_proj + b_proj  (fp32 out)
    mma_gemm_kernel<<<dim3(4096 / 128, 1024 / 128), 128, 81920>>>(
        yh, yl, wph, wpl, b_proj, out, nullptr, nullptr, 4096, 1024, 1024);
}

// round 8
// speedup vs baseline: 1.1521x; 1.1521x over previous
#include <cuda_runtime.h>
#include <cuda_bf16.h>
#include <cstdint>
#include <math.h>

// Problem constants: B=2, T=2048, C=1024, H=16, D=64, M = B*T = 4096

// ---------------------------------------------------------------------------
// Scratch (allocation forbidden -> device globals)
// ---------------------------------------------------------------------------
__device__ __nv_bfloat16 g_qkvh[4096 * 3072];     // qkv hi/lo bf16
__device__ __nv_bfloat16 g_qkvl[4096 * 3072];
__device__ __nv_bfloat16 g_xh[4096 * 1024];       // x hi/lo
__device__ __nv_bfloat16 g_xl[4096 * 1024];
__device__ __nv_bfloat16 g_wah[3072 * 1024];      // w_attn^T hi/lo  [N,K]
__device__ __nv_bfloat16 g_wal[3072 * 1024];
__device__ __nv_bfloat16 g_wph[1024 * 1024];      // w_proj^T hi/lo  [N,K]
__device__ __nv_bfloat16 g_wpl[1024 * 1024];
__device__ __nv_bfloat16 g_yh[4096 * 1024];       // attention out hi/lo
__device__ __nv_bfloat16 g_yl[4096 * 1024];

// ---------------------------------------------------------------------------
// PTX helpers (plain sm_100-safe: mma.sync + cp.async + ldmatrix)
// ---------------------------------------------------------------------------
__device__ __forceinline__ uint32_t smem_to_u32(const void* p) {
    uint32_t a;
    asm("{ .reg .u64 t; cvta.to.shared.u64 t, %1; cvt.u32.u64 %0, t; }" : "=r"(a) : "l"(p));
    return a;
}

#define CP_ASYNC16(dst_u32, src_ptr) \
    asm volatile("cp.async.cg.shared.global [%0], [%1], 16;" \
                 :: "r"(dst_u32), "l"(src_ptr) : "memory")
#define CP_COMMIT() asm volatile("cp.async.commit_group;" ::: "memory")
#define CP_WAIT(n)  asm volatile("cp.async.wait_group %0;" :: "n"(n) : "memory")

#define LDSM_X4(r0, r1, r2, r3, addr) \
    asm volatile("ldmatrix.sync.aligned.m8n8.x4.shared.b16 {%0,%1,%2,%3}, [%4];" \
                 : "=r"(r0), "=r"(r1), "=r"(r2), "=r"(r3) : "r"(addr))

#define LDSM_X4_TRANS(r0, r1, r2, r3, addr) \
    asm volatile("ldmatrix.sync.aligned.m8n8.x4.trans.shared.b16 {%0,%1,%2,%3}, [%4];" \
                 : "=r"(r0), "=r"(r1), "=r"(r2), "=r"(r3) : "r"(addr))

// mma.sync m16n8k16 row.col f32 += bf16 * bf16
#define MMA_BF16(c, a, b) \
    asm volatile("mma.sync.aligned.m16n8k16.row.col.f32.bf16.bf16.f32 " \
                 "{%0,%1,%2,%3}, {%4,%5,%6,%7}, {%8,%9}, {%0,%1,%2,%3};" \
                 : "+f"((c)[0]), "+f"((c)[1]), "+f"((c)[2]), "+f"((c)[3]) \
                 : "r"((a)[0]), "r"((a)[1]), "r"((a)[2]), "r"((a)[3]), \
                   "r"((b)[0]), "r"((b)[1]))

// fp32 pair -> (hi, lo) bf16x2 packed in u32
__device__ __forceinline__ void split2(float x, float y, uint32_t& h, uint32_t& l) {
    __nv_bfloat162 h2 = __floats2bfloat162_rn(x, y);
    __nv_bfloat162 l2 = __floats2bfloat162_rn(x - __bfloat162float(h2.x),
                                              y - __bfloat162float(h2.y));
    h = *(uint32_t*)&h2;
    l = *(uint32_t*)&l2;
}

// ---------------------------------------------------------------------------
// Pre-pass 1: elementwise fp32 -> (hi, lo) bf16 split
// ---------------------------------------------------------------------------
__global__ __launch_bounds__(256) void split_bf16_kernel(
    const float* __restrict__ in, __nv_bfloat16* __restrict__ hi,
    __nv_bfloat16* __restrict__ lo, int n4)
{
    int i = blockIdx.x * 256 + threadIdx.x;
    if (i >= n4) return;
    float4 v = ((const float4*)in)[i];
    uint32_t h0, l0, h1, l1;
    split2(v.x, v.y, h0, l0);
    split2(v.z, v.w, h1, l1);
    ((uint32_t*)hi)[i * 2 + 0] = h0;
    ((uint32_t*)hi)[i * 2 + 1] = h1;
    ((uint32_t*)lo)[i * 2 + 0] = l0;
    ((uint32_t*)lo)[i * 2 + 1] = l1;
}

// ---------------------------------------------------------------------------
// Pre-pass 2: W[K,N] fp32 -> W^T[N,K] (hi, lo) bf16. 32x32 tiles.
// ---------------------------------------------------------------------------
__global__ __launch_bounds__(256) void transpose_split_kernel(
    const float* __restrict__ W, __nv_bfloat16* __restrict__ Th,
    __nv_bfloat16* __restrict__ Tl, int K, int N)
{
    __shared__ float tile[32][33];
    const int n0 = blockIdx.x * 32;
    const int k0 = blockIdx.y * 32;
    const int tx = threadIdx.x, ty = threadIdx.y;
    #pragma unroll
    for (int j = 0; j < 4; j++) {
        int r = ty + j * 8;
        tile[r][tx] = W[(size_t)(k0 + r) * N + n0 + tx];
    }
    __syncthreads();
    #pragma unroll
    for (int j = 0; j < 4; j++) {
        int r = ty + j * 8;
        float v = tile[tx][r];
        __nv_bfloat16 h = __float2bfloat16_rn(v);
        __nv_bfloat16 l = __float2bfloat16_rn(v - __bfloat162float(h));
        Th[(size_t)(n0 + r) * K + k0 + tx] = h;
        Tl[(size_t)(n0 + r) * K + k0 + tx] = l;
    }
}

// ---------------------------------------------------------------------------
// Tensor-core GEMM (R6 config: 8 warps, 32x64 warp tiles) — 265us, tensor 55%
//   C = Ah@Wh^T + Ah@Wl^T + Al@Wh^T + bias
// ---------------------------------------------------------------------------
#define PITCH 40
#define TILE_BF16 (128 * PITCH)
#define BUF_BF16  (4 * TILE_BF16)

__global__ __launch_bounds__(256) void mma_gemm_kernel(
    const __nv_bfloat16* __restrict__ Ah, const __nv_bfloat16* __restrict__ Al,
    const __nv_bfloat16* __restrict__ Wh, const __nv_bfloat16* __restrict__ Wl,
    const float* __restrict__ bias, float* __restrict__ Cf,
    __nv_bfloat16* __restrict__ Ch, __nv_bfloat16* __restrict__ Cl,
    int M, int N, int K)
{
    extern __shared__ __align__(16) __nv_bfloat16 sm[];
    const uint32_t sbase = smem_to_u32(sm);
    const int tid = threadIdx.x;
    const int wid = tid >> 5, lane = tid & 31;
    const int wm = wid & 3;
    const int wn = wid >> 2;
    const int ra = lane >> 2;
    const int c2 = (lane & 3) * 2;
    const int m0 = blockIdx.x * 128;
    const int n0 = blockIdx.y * 128;

    const int r8 = lane & 7;
    const int s0 = (lane >> 3) & 1;
    const int s1 = (lane >> 4) & 1;
    const int rA = r8 + s0 * 8, kA = s1 * 8;
    const int rB = r8 + s1 * 8, kB = s0 * 8;

    const __nv_bfloat16* srcs[4] = {
        Ah + (size_t)m0 * K, Al + (size_t)m0 * K,
        Wh + (size_t)n0 * K, Wl + (size_t)n0 * K
    };

    float acc[2][8][4];
    #pragma unroll
    for (int mi = 0; mi < 2; mi++)
        #pragma unroll
        for (int ni = 0; ni < 8; ni++)
            #pragma unroll
            for (int q = 0; q < 4; q++) acc[mi][ni][q] = 0.f;

    const int NCH = K >> 5;

    auto issue_chunk = [&](int ch, int buf) {
        const int k0 = ch * 32;
        #pragma unroll
        for (int t = 0; t < 4; t++) {
            const __nv_bfloat16* src0 = srcs[t] + k0;
            const uint32_t dst0 = sbase + (buf * BUF_BF16 + t * TILE_BF16) * 2;
            #pragma unroll
            for (int i = 0; i < 2; i++) {
                int idx = tid + i * 256;
                int row = idx >> 2, seg = idx & 3;
                CP_ASYNC16(dst0 + (row * PITCH + seg * 8) * 2,
                           src0 + (size_t)row * K + seg * 8);
            }
        }
    };

    issue_chunk(0, 0);
    CP_COMMIT();

    for (int ch = 0; ch < NCH; ch++) {
        const int buf = ch & 1;
        if (ch + 1 < NCH) {
            issue_chunk(ch + 1, buf ^ 1);
            CP_COMMIT();
            CP_WAIT(1);
        } else {
            CP_WAIT(0);
        }
        __syncthreads();

        const uint32_t boff = sbase + buf * BUF_BF16 * 2;
        #pragma unroll
        for (int ks = 0; ks < 2; ks++) {
            uint32_t ah[2][4], al[2][4], bh[8][2], bl[8][2];
            #pragma unroll
            for (int mi = 0; mi < 2; mi++) {
                const int row = wm * 32 + mi * 16 + rA;
                const uint32_t adr = boff + (row * PITCH + ks * 16 + kA) * 2;
                LDSM_X4(ah[mi][0], ah[mi][1], ah[mi][2], ah[mi][3], adr);
                LDSM_X4(al[mi][0], al[mi][1], al[mi][2], al[mi][3],
                        adr + TILE_BF16 * 2);
            }
            #pragma unroll
            for (int np = 0; np < 4; np++) {
                const int row = wn * 64 + np * 16 + rB;
                const uint32_t adr = boff + 2 * TILE_BF16 * 2 +
                                     (row * PITCH + ks * 16 + kB) * 2;
                LDSM_X4(bh[2 * np][0], bh[2 * np][1],
                        bh[2 * np + 1][0], bh[2 * np + 1][1], adr);
                LDSM_X4(bl[2 * np][0], bl[2 * np][1],
                        bl[2 * np + 1][0], bl[2 * np + 1][1],
                        adr + TILE_BF16 * 2);
            }
            #pragma unroll
            for (int mi = 0; mi < 2; mi++)
                #pragma unroll
                for (int ni = 0; ni < 8; ni++) {
                    MMA_BF16(acc[mi][ni], ah[mi], bh[ni]);
                    MMA_BF16(acc[mi][ni], ah[mi], bl[ni]);
                    MMA_BF16(acc[mi][ni], al[mi], bh[ni]);
                }
        }
        __syncthreads();
    }

    // Epilogue
    #pragma unroll
    for (int ni = 0; ni < 8; ni++) {
        const int col = n0 + wn * 64 + ni * 8 + c2;
        const float bv0 = bias[col], bv1 = bias[col + 1];
        #pragma unroll
        for (int mi = 0; mi < 2; mi++) {
            const int r0 = m0 + wm * 32 + mi * 16 + ra;
            const float v00 = acc[mi][ni][0] + bv0, v01 = acc[mi][ni][1] + bv1;
            const float v10 = acc[mi][ni][2] + bv0, v11 = acc[mi][ni][3] + bv1;
            if (Ch) {
                uint32_t h0, l0, h1, l1;
                split2(v00, v01, h0, l0);
                split2(v10, v11, h1, l1);
                *(uint32_t*)(Ch + (size_t)r0 * N + col) = h0;
                *(uint32_t*)(Cl + (size_t)r0 * N + col) = l0;
                *(uint32_t*)(Ch + (size_t)(r0 + 8) * N + col) = h1;
                *(uint32_t*)(Cl + (size_t)(r0 + 8) * N + col) = l1;
            } else {
                *(float2*)(Cf + (size_t)r0 * N + col) = make_float2(v00, v01);
                *(float2*)(Cf + (size_t)(r0 + 8) * N + col) = make_float2(v10, v11);
            }
        }
    }
}

// ---------------------------------------------------------------------------
// Tensor-core causal flash attention (8 warps x 16 q-rows, CTA 128x64-keys).
// New in R8: V stored NATURALLY + ldmatrix.x4.trans for PV B-frags;
//            cp.async double-buffered K/V tiles over the kt loop.
// smem (bf16, pitch 72): Qh[128] Ql[128] @ 0/9216;
//   KV buffers @ 18432 + buf*18432: Kh[64] Kl[64] Vh[64] Vl[64]
//   (4608 bf16 each). Total 55296 bf16 = 110592 B.
// ---------------------------------------------------------------------------
#define AP 72
#define AQH 0
#define AQL 9216
#define AKV0 18432                               // first KV buffer (bf16 units)
#define AKVSTRIDE 18432                          // per-buffer stride
#define AKH 0
#define AKL 4608
#define AVH 9216
#define AVL 13824

__global__ __launch_bounds__(256) void attn_mma_kernel(
    const __nv_bfloat16* __restrict__ qh, const __nv_bfloat16* __restrict__ ql,
    __nv_bfloat16* __restrict__ yh, __nv_bfloat16* __restrict__ yl)
{
    extern __shared__ __align__(16) __nv_bfloat16 sma[];
    const uint32_t sbase = smem_to_u32(sma);
    const int tid = threadIdx.x;
    const int wid = tid >> 5, lane = tid & 31;
    const int gr = lane >> 2;
    const int gc = lane & 3;
    const int qt = gridDim.x - 1 - blockIdx.x;    // heavy CTAs first
    const int h  = blockIdx.y;
    const int b  = blockIdx.z;
    const int wq = wid * 16;

    const int r8 = lane & 7;
    const int s0 = (lane >> 3) & 1;
    const int s1 = (lane >> 4) & 1;
    const int rA = r8 + s0 * 8, kA = s1 * 8;      // also V-trans geometry
    const int rB = r8 + s1 * 8, kB = s0 * 8;

    const float SSCALE = 0.125f * 1.44269504088896f;  // 1/sqrt(64)*log2(e)

    const size_t kcol = (size_t)(b * 2048) * 3072 + 1024 + h * 64;
    const size_t vcol = kcol + 1024;

    // cp.async one K/V tile pair (hi+lo) for key-tile kt into buffer buf
    auto issue_kv = [&](int kt, int buf) {
        const uint32_t bb = sbase + (AKV0 + buf * AKVSTRIDE) * 2;
        #pragma unroll
        for (int i = 0; i < 2; i++) {
            int f = tid + i * 256;                // 0..511
            int j = f >> 3, seg = f & 7;
            const size_t off = (size_t)(kt * 64 + j) * 3072 + seg * 8;
            const uint32_t d = (j * AP + seg * 8) * 2;
            CP_ASYNC16(bb + AKH * 2 + d, qh + kcol + off);
            CP_ASYNC16(bb + AKL * 2 + d, ql + kcol + off);
            CP_ASYNC16(bb + AVH * 2 + d, qh + vcol + off);
            CP_ASYNC16(bb + AVL * 2 + d, ql + vcol + off);
        }
    };

    // ---- Load Q tile (128 x 64 bf16 hi/lo), plain vector loads ----
    {
        const size_t qrow = (size_t)(b * 2048 + qt * 128) * 3072 + h * 64;
        #pragma unroll
        for (int i = 0; i < 4; i++) {
            int f = tid + i * 256;                // 0..1023
            int r = f >> 3, seg = f & 7;
            const size_t off = qrow + (size_t)r * 3072 + seg * 8;
            *(uint4*)&sma[AQH + r * AP + seg * 8] = *(const uint4*)(qh + off);
            *(uint4*)&sma[AQL + r * AP + seg * 8] = *(const uint4*)(ql + off);
        }
    }

    float o[8][4];
    #pragma unroll
    for (int j = 0; j < 8; j++)
        #pragma unroll
        for (int q = 0; q < 4; q++) o[j][q] = 0.f;
    float mrow[2] = {-1e30f, -1e30f};
    float lrow[2] = {0.f, 0.f};

    const int kt_max = 2 * qt + 1;

    issue_kv(0, 0);
    CP_COMMIT();

    for (int kt = 0; kt <= kt_max; kt++) {
        const int buf = kt & 1;
        if (kt < kt_max) {
            issue_kv(kt + 1, buf ^ 1);
            CP_COMMIT();
            CP_WAIT(1);
        } else {
            CP_WAIT(0);
        }
        __syncthreads();

        const uint32_t kvb = sbase + (AKV0 + buf * AKVSTRIDE) * 2;

        // ---- S = Q K^T (16x64 per warp), hi/lo 3-product ----
        float s[8][4];
        #pragma unroll
        for (int j = 0; j < 8; j++)
            #pragma unroll
            for (int q = 0; q < 4; q++) s[j][q] = 0.f;

        #pragma unroll
        for (int ks = 0; ks < 4; ks++) {
            uint32_t ah[4], al[4], bh[8][2], bl[8][2];
            {
                const uint32_t adr = sbase +
                    (AQH + (wq + rA) * AP + ks * 16 + kA) * 2;
                LDSM_X4(ah[0], ah[1], ah[2], ah[3], adr);
                LDSM_X4(al[0], al[1], al[2], al[3], adr + (AQL - AQH) * 2);
            }
            #pragma unroll
            for (int np = 0; np < 4; np++) {
                const uint32_t adr = kvb + AKH * 2 +
                    ((np * 16 + rB) * AP + ks * 16 + kB) * 2;
                LDSM_X4(bh[2 * np][0], bh[2 * np][1],
                        bh[2 * np + 1][0], bh[2 * np + 1][1], adr);
                LDSM_X4(bl[2 * np][0], bl[2 * np][1],
                        bl[2 * np + 1][0], bl[2 * np + 1][1],
                        adr + (AKL - AKH) * 2);
            }
            #pragma unroll
            for (int j = 0; j < 8; j++) {
                MMA_BF16(s[j], ah, bh[j]);
                MMA_BF16(s[j], ah, bl[j]);
                MMA_BF16(s[j], al, bh[j]);
            }
        }

        // ---- Scale + causal mask ----
        #pragma unroll
        for (int j = 0; j < 8; j++)
            #pragma unroll
            for (int q = 0; q < 4; q++) s[j][q] *= SSCALE;

        if (kt >= 2 * qt) {
            const int row0 = qt * 128 + wq + gr;
            #pragma unroll
            for (int j = 0; j < 8; j++) {
                const int col = kt * 64 + j * 8 + 2 * gc;
                if (col > row0)         s[j][0] = -1e30f;
                if (col + 1 > row0)     s[j][1] = -1e30f;
                if (col > row0 + 8)     s[j][2] = -1e30f;
                if (col + 1 > row0 + 8) s[j][3] = -1e30f;
            }
        }

        // ---- Online softmax ----
        #pragma unroll
        for (int i = 0; i < 2; i++) {
            const int q0i = i * 2;
            float mx = -1e30f;
            #pragma unroll
            for (int j = 0; j < 8; j++)
                mx = fmaxf(mx, fmaxf(s[j][q0i], s[j][q0i + 1]));
            mx = fmaxf(mx, __shfl_xor_sync(0xffffffffu, mx, 1));
            mx = fmaxf(mx, __shfl_xor_sync(0xffffffffu, mx, 2));
            const float mnew = fmaxf(mrow[i], mx);
            const float alpha = exp2f(mrow[i] - mnew);
            float rsum = 0.f;
            #pragma unroll
            for (int j = 0; j < 8; j++) {
                s[j][q0i]     = exp2f(s[j][q0i] - mnew);
                s[j][q0i + 1] = exp2f(s[j][q0i + 1] - mnew);
                rsum += s[j][q0i] + s[j][q0i + 1];
            }
            rsum += __shfl_xor_sync(0xffffffffu, rsum, 1);
            rsum += __shfl_xor_sync(0xffffffffu, rsum, 2);
            lrow[i] = lrow[i] * alpha + rsum;
            mrow[i] = mnew;
            #pragma unroll
            for (int j = 0; j < 8; j++) {
                o[j][q0i]     *= alpha;
                o[j][q0i + 1] *= alpha;
            }
        }

        // ---- Pack P hi/lo A-fragments ----
        uint32_t pha[4][4], pla[4][4];
        #pragma unroll
        for (int t = 0; t < 4; t++) {
            split2(s[2 * t][0],     s[2 * t][1],     pha[t][0], pla[t][0]);
            split2(s[2 * t][2],     s[2 * t][3],     pha[t][1], pla[t][1]);
            split2(s[2 * t + 1][0], s[2 * t + 1][1], pha[t][2], pla[t][2]);
            split2(s[2 * t + 1][2], s[2 * t + 1][3], pha[t][3], pla[t][3]);
        }

        // ---- O += P V   (V natural in smem; B-frags via ldmatrix.trans) ----
        #pragma unroll
        for (int t = 0; t < 4; t++) {
            uint32_t bvh[8][2], bvl[8][2];
            #pragma unroll
            for (int np = 0; np < 4; np++) {
                const uint32_t adr = kvb + AVH * 2 +
                    ((t * 16 + rA) * AP + np * 16 + kA) * 2;
                LDSM_X4_TRANS(bvh[2 * np][0], bvh[2 * np][1],
                              bvh[2 * np + 1][0], bvh[2 * np + 1][1], adr);
                LDSM_X4_TRANS(bvl[2 * np][0], bvl[2 * np][1],
                              bvl[2 * np + 1][0], bvl[2 * np + 1][1],
                              adr + (AVL - AVH) * 2);
            }
            #pragma unroll
            for (int j = 0; j < 8; j++) {
                MMA_BF16(o[j], pha[t], bvh[j]);
                MMA_BF16(o[j], pha[t], bvl[j]);
                MMA_BF16(o[j], pla[t], bvh[j]);
            }
        }
        __syncthreads();
    }

    // ---- Epilogue: normalize, hi/lo split, store bf16 ----
    const float inv0 = 1.0f / lrow[0];
    const float inv1 = 1.0f / lrow[1];
    const int row0 = b * 2048 + qt * 128 + wq + gr;
    #pragma unroll
    for (int j = 0; j < 8; j++) {
        const int col = h * 64 + j * 8 + 2 * gc;
        uint32_t h0, l0, h1, l1;
        split2(o[j][0] * inv0, o[j][1] * inv0, h0, l0);
        split2(o[j][2] * inv1, o[j][3] * inv1, h1, l1);
        *(uint32_t*)(yh + (size_t)row0 * 1024 + col) = h0;
        *(uint32_t*)(yl + (size_t)row0 * 1024 + col) = l0;
        *(uint32_t*)(yh + (size_t)(row0 + 8) * 1024 + col) = h1;
        *(uint32_t*)(yl + (size_t)(row0 + 8) * 1024 + col) = l1;
    }
}

// ---------------------------------------------------------------------------
// Launch
// ---------------------------------------------------------------------------
extern "C" void kernel_launch(void* const* d_in, const int* in_sizes, int n_in,
                              void* d_out, int out_size)
{
    const float* x      = (const float*)d_in[0];   // [2,2048,1024]
    const float* w_attn = (const float*)d_in[1];   // [1024,3072]
    const float* b_attn = (const float*)d_in[2];   // [3072]
    const float* w_proj = (const float*)d_in[3];   // [1024,1024]
    const float* b_proj = (const float*)d_in[4];   // [1024]
    float* out = (float*)d_out;                    // [2,2048,1024]

    __nv_bfloat16 *qkvh, *qkvl, *xh, *xl, *wah, *wal, *wph, *wpl, *yh, *yl;
    cudaGetSymbolAddress((void**)&qkvh, g_qkvh);
    cudaGetSymbolAddress((void**)&qkvl, g_qkvl);
    cudaGetSymbolAddress((void**)&xh,  g_xh);
    cudaGetSymbolAddress((void**)&xl,  g_xl);
    cudaGetSymbolAddress((void**)&wah, g_wah);
    cudaGetSymbolAddress((void**)&wal, g_wal);
    cudaGetSymbolAddress((void**)&wph, g_wph);
    cudaGetSymbolAddress((void**)&wpl, g_wpl);
    cudaGetSymbolAddress((void**)&yh,  g_yh);
    cudaGetSymbolAddress((void**)&yl,  g_yl);

    cudaFuncSetAttribute(mma_gemm_kernel,
                         cudaFuncAttributeMaxDynamicSharedMemorySize, 81920);
    cudaFuncSetAttribute(attn_mma_kernel,
                         cudaFuncAttributeMaxDynamicSharedMemorySize, 110592);

    // Pre-pass: split x, transpose+split weights
    split_bf16_kernel<<<4096, 256>>>(x, xh, xl, 4096 * 1024 / 4);
    transpose_split_kernel<<<dim3(3072 / 32, 1024 / 32), dim3(32, 8)>>>(
        w_attn, wah, wal, 1024, 3072);
    transpose_split_kernel<<<dim3(1024 / 32, 1024 / 32), dim3(32, 8)>>>(
        w_proj, wph, wpl, 1024, 1024);

    // 1) qkv = x @ w_attn + b_attn  -> hi/lo bf16 directly
    mma_gemm_kernel<<<dim3(4096 / 128, 3072 / 128), 256, 81920>>>(
        xh, xl, wah, wal, b_attn, nullptr, qkvh, qkvl, 4096, 3072, 1024);

    // 2) causal attention -> yh/yl (bf16 in, bf16 out)
    attn_mma_kernel<<<dim3(2048 / 128, 16, 2), 256, 110592>>>(qkvh, qkvl, yh, yl);

    // 3) out = y @ w_proj + b_proj  (fp32 out)
    mma_gemm_kernel<<<dim3(4096 / 128, 1024 / 128), 256, 81920>>>(
        yh, yl, wph, wpl, b_proj, out, nullptr, nullptr, 4096, 1024, 1024);
}

// round 11
// speedup vs baseline: 1.3734x; 1.1920x over previous
#include <cuda_runtime.h>
#include <cuda_bf16.h>
#include <cuda_fp16.h>
#include <cstdint>
#include <math.h>

// Problem constants: B=2, T=2048, C=1024, H=16, D=64, M = B*T = 4096

// ---------------------------------------------------------------------------
// Scratch (allocation forbidden -> device globals)
// ---------------------------------------------------------------------------
__device__ __nv_bfloat16 g_qkvh[4096 * 3072];     // qkv hi/lo bf16 (attn input)
__device__ __nv_bfloat16 g_qkvl[4096 * 3072];
__device__ __half g_xh[4096 * 1024];              // x hi/lo fp16
__device__ __half g_xl[4096 * 1024];
__device__ __half g_wa[3072 * 1024];              // w_attn^T fp16  [N,K]
__device__ __half g_wp[1024 * 1024];              // w_proj^T fp16  [N,K]
__device__ __half g_yh[4096 * 1024];              // attention out hi/lo fp16
__device__ __half g_yl[4096 * 1024];

// ---------------------------------------------------------------------------
// PTX helpers (plain sm_100-safe: mma.sync + cp.async + ldmatrix)
// ---------------------------------------------------------------------------
__device__ __forceinline__ uint32_t smem_to_u32(const void* p) {
    uint32_t a;
    asm("{ .reg .u64 t; cvta.to.shared.u64 t, %1; cvt.u32.u64 %0, t; }" : "=r"(a) : "l"(p));
    return a;
}

#define CP_ASYNC16(dst_u32, src_ptr) \
    asm volatile("cp.async.cg.shared.global [%0], [%1], 16;" \
                 :: "r"(dst_u32), "l"(src_ptr) : "memory")
#define CP_COMMIT() asm volatile("cp.async.commit_group;" ::: "memory")
#define CP_WAIT(n)  asm volatile("cp.async.wait_group %0;" :: "n"(n) : "memory")

#define LDSM_X4(r0, r1, r2, r3, addr) \
    asm volatile("ldmatrix.sync.aligned.m8n8.x4.shared.b16 {%0,%1,%2,%3}, [%4];" \
                 : "=r"(r0), "=r"(r1), "=r"(r2), "=r"(r3) : "r"(addr))

#define LDSM_X4_TRANS(r0, r1, r2, r3, addr) \
    asm volatile("ldmatrix.sync.aligned.m8n8.x4.trans.shared.b16 {%0,%1,%2,%3}, [%4];" \
                 : "=r"(r0), "=r"(r1), "=r"(r2), "=r"(r3) : "r"(addr))

// mma.sync m16n8k16 row.col f32 accumulators
#define MMA_BF16(c, a, b) \
    asm volatile("mma.sync.aligned.m16n8k16.row.col.f32.bf16.bf16.f32 " \
                 "{%0,%1,%2,%3}, {%4,%5,%6,%7}, {%8,%9}, {%0,%1,%2,%3};" \
                 : "+f"((c)[0]), "+f"((c)[1]), "+f"((c)[2]), "+f"((c)[3]) \
                 : "r"((a)[0]), "r"((a)[1]), "r"((a)[2]), "r"((a)[3]), \
                   "r"((b)[0]), "r"((b)[1]))

#define MMA_FP16(c, a, b) \
    asm volatile("mma.sync.aligned.m16n8k16.row.col.f32.f16.f16.f32 " \
                 "{%0,%1,%2,%3}, {%4,%5,%6,%7}, {%8,%9}, {%0,%1,%2,%3};" \
                 : "+f"((c)[0]), "+f"((c)[1]), "+f"((c)[2]), "+f"((c)[3]) \
                 : "r"((a)[0]), "r"((a)[1]), "r"((a)[2]), "r"((a)[3]), \
                   "r"((b)[0]), "r"((b)[1]))

// fp32 pair -> (hi, lo) bf16x2 packed in u32
__device__ __forceinline__ void split2(float x, float y, uint32_t& h, uint32_t& l) {
    __nv_bfloat162 h2 = __floats2bfloat162_rn(x, y);
    __nv_bfloat162 l2 = __floats2bfloat162_rn(x - __bfloat162float(h2.x),
                                              y - __bfloat162float(h2.y));
    h = *(uint32_t*)&h2;
    l = *(uint32_t*)&l2;
}

// fp32 pair -> (hi, lo) fp16x2 packed in u32
__device__ __forceinline__ void split2h(float x, float y, uint32_t& h, uint32_t& l) {
    __half2 h2 = __floats2half2_rn(x, y);
    __half2 l2 = __floats2half2_rn(x - __half2float(__low2half(h2)),
                                   y - __half2float(__high2half(h2)));
    h = *(uint32_t*)&h2;
    l = *(uint32_t*)&l2;
}

// ---------------------------------------------------------------------------
// Pre-pass 1: elementwise fp32 -> (hi, lo) fp16 split
// ---------------------------------------------------------------------------
__global__ __launch_bounds__(256) void split_fp16_kernel(
    const float* __restrict__ in, __half* __restrict__ hi,
    __half* __restrict__ lo, int n4)
{
    int i = blockIdx.x * 256 + threadIdx.x;
    if (i >= n4) return;
    float4 v = ((const float4*)in)[i];
    uint32_t h0, l0, h1, l1;
    split2h(v.x, v.y, h0, l0);
    split2h(v.z, v.w, h1, l1);
    ((uint32_t*)hi)[i * 2 + 0] = h0;
    ((uint32_t*)hi)[i * 2 + 1] = h1;
    ((uint32_t*)lo)[i * 2 + 0] = l0;
    ((uint32_t*)lo)[i * 2 + 1] = l1;
}

// ---------------------------------------------------------------------------
// Pre-pass 2: W[K,N] fp32 -> W^T[N,K] single fp16. 32x32 tiles.
// ---------------------------------------------------------------------------
__global__ __launch_bounds__(256) void transpose_fp16_kernel(
    const float* __restrict__ W, __half* __restrict__ Th, int K, int N)
{
    __shared__ float tile[32][33];
    const int n0 = blockIdx.x * 32;
    const int k0 = blockIdx.y * 32;
    const int tx = threadIdx.x, ty = threadIdx.y;
    #pragma unroll
    for (int j = 0; j < 4; j++) {
        int r = ty + j * 8;
        tile[r][tx] = W[(size_t)(k0 + r) * N + n0 + tx];
    }
    __syncthreads();
    #pragma unroll
    for (int j = 0; j < 4; j++) {
        int r = ty + j * 8;
        Th[(size_t)(n0 + r) * K + k0 + tx] = __float2half_rn(tile[tx][r]);
    }
}

// ---------------------------------------------------------------------------
// Tensor-core GEMM, fp16 2-product: C = Ah@W^T + Al@W^T + bias
// A split fp16 hi/lo (A-side ~exact), W single fp16 (error ~2^-11).
// 8 warps, 32x64 warp tiles, CTA 128x128, K-chunk 32, cp.async double buffer.
// smem: 2 buffers x 3 tiles x 128x40 fp16 = 61440 B.
// ---------------------------------------------------------------------------
#define PITCH 40
#define TILE_H (128 * PITCH)
#define BUF_H  (3 * TILE_H)

__global__ __launch_bounds__(256) void mma_gemm_kernel(
    const __half* __restrict__ Ah, const __half* __restrict__ Al,
    const __half* __restrict__ W,
    const float* __restrict__ bias, float* __restrict__ Cf,
    __nv_bfloat16* __restrict__ Ch, __nv_bfloat16* __restrict__ Cl,
    int M, int N, int K)
{
    extern __shared__ __align__(16) __half sm[];
    const uint32_t sbase = smem_to_u32(sm);
    const int tid = threadIdx.x;
    const int wid = tid >> 5, lane = tid & 31;
    const int wm = wid & 3;
    const int wn = wid >> 2;
    const int ra = lane >> 2;
    const int c2 = (lane & 3) * 2;
    const int m0 = blockIdx.x * 128;
    const int n0 = blockIdx.y * 128;

    const int r8 = lane & 7;
    const int s0 = (lane >> 3) & 1;
    const int s1 = (lane >> 4) & 1;
    const int rA = r8 + s0 * 8, kA = s1 * 8;
    const int rB = r8 + s1 * 8, kB = s0 * 8;

    const __half* srcs[3] = {
        Ah + (size_t)m0 * K, Al + (size_t)m0 * K, W + (size_t)n0 * K
    };

    float acc[2][8][4];
    #pragma unroll
    for (int mi = 0; mi < 2; mi++)
        #pragma unroll
        for (int ni = 0; ni < 8; ni++)
            #pragma unroll
            for (int q = 0; q < 4; q++) acc[mi][ni][q] = 0.f;

    const int NCH = K >> 5;

    auto issue_chunk = [&](int ch, int buf) {
        const int k0 = ch * 32;
        #pragma unroll
        for (int t = 0; t < 3; t++) {
            const __half* src0 = srcs[t] + k0;
            const uint32_t dst0 = sbase + (buf * BUF_H + t * TILE_H) * 2;
            #pragma unroll
            for (int i = 0; i < 2; i++) {
                int idx = tid + i * 256;
                int row = idx >> 2, seg = idx & 3;
                CP_ASYNC16(dst0 + (row * PITCH + seg * 8) * 2,
                           src0 + (size_t)row * K + seg * 8);
            }
        }
    };

    issue_chunk(0, 0);
    CP_COMMIT();

    for (int ch = 0; ch < NCH; ch++) {
        const int buf = ch & 1;
        if (ch + 1 < NCH) {
            issue_chunk(ch + 1, buf ^ 1);
            CP_COMMIT();
            CP_WAIT(1);
        } else {
            CP_WAIT(0);
        }
        __syncthreads();

        const uint32_t boff = sbase + buf * BUF_H * 2;
        #pragma unroll
        for (int ks = 0; ks < 2; ks++) {
            uint32_t ah[2][4], al[2][4], bw[8][2];
            #pragma unroll
            for (int mi = 0; mi < 2; mi++) {
                const int row = wm * 32 + mi * 16 + rA;
                const uint32_t adr = boff + (row * PITCH + ks * 16 + kA) * 2;
                LDSM_X4(ah[mi][0], ah[mi][1], ah[mi][2], ah[mi][3], adr);
                LDSM_X4(al[mi][0], al[mi][1], al[mi][2], al[mi][3],
                        adr + TILE_H * 2);
            }
            #pragma unroll
            for (int np = 0; np < 4; np++) {
                const int row = wn * 64 + np * 16 + rB;
                const uint32_t adr = boff + 2 * TILE_H * 2 +
                                     (row * PITCH + ks * 16 + kB) * 2;
                LDSM_X4(bw[2 * np][0], bw[2 * np][1],
                        bw[2 * np + 1][0], bw[2 * np + 1][1], adr);
            }
            #pragma unroll
            for (int mi = 0; mi < 2; mi++)
                #pragma unroll
                for (int ni = 0; ni < 8; ni++) {
                    MMA_FP16(acc[mi][ni], ah[mi], bw[ni]);
                    MMA_FP16(acc[mi][ni], al[mi], bw[ni]);
                }
        }
        __syncthreads();
    }

    // Epilogue
    #pragma unroll
    for (int ni = 0; ni < 8; ni++) {
        const int col = n0 + wn * 64 + ni * 8 + c2;
        const float bv0 = bias[col], bv1 = bias[col + 1];
        #pragma unroll
        for (int mi = 0; mi < 2; mi++) {
            const int r0 = m0 + wm * 32 + mi * 16 + ra;
            const float v00 = acc[mi][ni][0] + bv0, v01 = acc[mi][ni][1] + bv1;
            const float v10 = acc[mi][ni][2] + bv0, v11 = acc[mi][ni][3] + bv1;
            if (Ch) {
                uint32_t h0, l0, h1, l1;
                split2(v00, v01, h0, l0);
                split2(v10, v11, h1, l1);
                *(uint32_t*)(Ch + (size_t)r0 * N + col) = h0;
                *(uint32_t*)(Cl + (size_t)r0 * N + col) = l0;
                *(uint32_t*)(Ch + (size_t)(r0 + 8) * N + col) = h1;
                *(uint32_t*)(Cl + (size_t)(r0 + 8) * N + col) = l1;
            } else {
                *(float2*)(Cf + (size_t)r0 * N + col) = make_float2(v00, v01);
                *(float2*)(Cf + (size_t)(r0 + 8) * N + col) = make_float2(v10, v11);
            }
        }
    }
}

// ---------------------------------------------------------------------------
// Tensor-core causal flash attention (unchanged math from R8: bf16 3-product,
// cp.async K/V double buffer, natural-V + ldmatrix.trans).
// Epilogue emits fp16 hi/lo (proj input).
// ---------------------------------------------------------------------------
#define AP 72
#define AQH 0
#define AQL 9216
#define AKV0 18432
#define AKVSTRIDE 18432
#define AKH 0
#define AKL 4608
#define AVH 9216
#define AVL 13824

__global__ __launch_bounds__(256) void attn_mma_kernel(
    const __nv_bfloat16* __restrict__ qh, const __nv_bfloat16* __restrict__ ql,
    __half* __restrict__ yh, __half* __restrict__ yl)
{
    extern __shared__ __align__(16) __nv_bfloat16 sma[];
    const uint32_t sbase = smem_to_u32(sma);
    const int tid = threadIdx.x;
    const int wid = tid >> 5, lane = tid & 31;
    const int gr = lane >> 2;
    const int gc = lane & 3;
    const int qt = gridDim.x - 1 - blockIdx.x;    // heavy CTAs first
    const int h  = blockIdx.y;
    const int b  = blockIdx.z;
    const int wq = wid * 16;

    const int r8 = lane & 7;
    const int s0 = (lane >> 3) & 1;
    const int s1 = (lane >> 4) & 1;
    const int rA = r8 + s0 * 8, kA = s1 * 8;
    const int rB = r8 + s1 * 8, kB = s0 * 8;

    const float SSCALE = 0.125f * 1.44269504088896f;  // 1/sqrt(64)*log2(e)

    const size_t kcol = (size_t)(b * 2048) * 3072 + 1024 + h * 64;
    const size_t vcol = kcol + 1024;

    auto issue_kv = [&](int kt, int buf) {
        const uint32_t bb = sbase + (AKV0 + buf * AKVSTRIDE) * 2;
        #pragma unroll
        for (int i = 0; i < 2; i++) {
            int f = tid + i * 256;
            int j = f >> 3, seg = f & 7;
            const size_t off = (size_t)(kt * 64 + j) * 3072 + seg * 8;
            const uint32_t d = (j * AP + seg * 8) * 2;
            CP_ASYNC16(bb + AKH * 2 + d, qh + kcol + off);
            CP_ASYNC16(bb + AKL * 2 + d, ql + kcol + off);
            CP_ASYNC16(bb + AVH * 2 + d, qh + vcol + off);
            CP_ASYNC16(bb + AVL * 2 + d, ql + vcol + off);
        }
    };

    // Load Q tile (128 x 64 bf16 hi/lo)
    {
        const size_t qrow = (size_t)(b * 2048 + qt * 128) * 3072 + h * 64;
        #pragma unroll
        for (int i = 0; i < 4; i++) {
            int f = tid + i * 256;
            int r = f >> 3, seg = f & 7;
            const size_t off = qrow + (size_t)r * 3072 + seg * 8;
            *(uint4*)&sma[AQH + r * AP + seg * 8] = *(const uint4*)(qh + off);
            *(uint4*)&sma[AQL + r * AP + seg * 8] = *(const uint4*)(ql + off);
        }
    }

    float o[8][4];
    #pragma unroll
    for (int j = 0; j < 8; j++)
        #pragma unroll
        for (int q = 0; q < 4; q++) o[j][q] = 0.f;
    float mrow[2] = {-1e30f, -1e30f};
    float lrow[2] = {0.f, 0.f};

    const int kt_max = 2 * qt + 1;

    issue_kv(0, 0);
    CP_COMMIT();

    for (int kt = 0; kt <= kt_max; kt++) {
        const int buf = kt & 1;
        if (kt < kt_max) {
            issue_kv(kt + 1, buf ^ 1);
            CP_COMMIT();
            CP_WAIT(1);
        } else {
            CP_WAIT(0);
        }
        __syncthreads();

        const uint32_t kvb = sbase + (AKV0 + buf * AKVSTRIDE) * 2;

        // S = Q K^T, hi/lo 3-product
        float s[8][4];
        #pragma unroll
        for (int j = 0; j < 8; j++)
            #pragma unroll
            for (int q = 0; q < 4; q++) s[j][q] = 0.f;

        #pragma unroll
        for (int ks = 0; ks < 4; ks++) {
            uint32_t ah[4], al[4], bh[8][2], bl[8][2];
            {
                const uint32_t adr = sbase +
                    (AQH + (wq + rA) * AP + ks * 16 + kA) * 2;
                LDSM_X4(ah[0], ah[1], ah[2], ah[3], adr);
                LDSM_X4(al[0], al[1], al[2], al[3], adr + (AQL - AQH) * 2);
            }
            #pragma unroll
            for (int np = 0; np < 4; np++) {
                const uint32_t adr = kvb + AKH * 2 +
                    ((np * 16 + rB) * AP + ks * 16 + kB) * 2;
                LDSM_X4(bh[2 * np][0], bh[2 * np][1],
                        bh[2 * np + 1][0], bh[2 * np + 1][1], adr);
                LDSM_X4(bl[2 * np][0], bl[2 * np][1],
                        bl[2 * np + 1][0], bl[2 * np + 1][1],
                        adr + (AKL - AKH) * 2);
            }
            #pragma unroll
            for (int j = 0; j < 8; j++) {
                MMA_BF16(s[j], ah, bh[j]);
                MMA_BF16(s[j], ah, bl[j]);
                MMA_BF16(s[j], al, bh[j]);
            }
        }

        // Scale + causal mask
        #pragma unroll
        for (int j = 0; j < 8; j++)
            #pragma unroll
            for (int q = 0; q < 4; q++) s[j][q] *= SSCALE;

        if (kt >= 2 * qt) {
            const int row0 = qt * 128 + wq + gr;
            #pragma unroll
            for (int j = 0; j < 8; j++) {
                const int col = kt * 64 + j * 8 + 2 * gc;
                if (col > row0)         s[j][0] = -1e30f;
                if (col + 1 > row0)     s[j][1] = -1e30f;
                if (col > row0 + 8)     s[j][2] = -1e30f;
                if (col + 1 > row0 + 8) s[j][3] = -1e30f;
            }
        }

        // Online softmax
        #pragma unroll
        for (int i = 0; i < 2; i++) {
            const int q0i = i * 2;
            float mx = -1e30f;
            #pragma unroll
            for (int j = 0; j < 8; j++)
                mx = fmaxf(mx, fmaxf(s[j][q0i], s[j][q0i + 1]));
            mx = fmaxf(mx, __shfl_xor_sync(0xffffffffu, mx, 1));
            mx = fmaxf(mx, __shfl_xor_sync(0xffffffffu, mx, 2));
            const float mnew = fmaxf(mrow[i], mx);
            const float alpha = exp2f(mrow[i] - mnew);
            float rsum = 0.f;
            #pragma unroll
            for (int j = 0; j < 8; j++) {
                s[j][q0i]     = exp2f(s[j][q0i] - mnew);
                s[j][q0i + 1] = exp2f(s[j][q0i + 1] - mnew);
                rsum += s[j][q0i] + s[j][q0i + 1];
            }
            rsum += __shfl_xor_sync(0xffffffffu, rsum, 1);
            rsum += __shfl_xor_sync(0xffffffffu, rsum, 2);
            lrow[i] = lrow[i] * alpha + rsum;
            mrow[i] = mnew;
            #pragma unroll
            for (int j = 0; j < 8; j++) {
                o[j][q0i]     *= alpha;
                o[j][q0i + 1] *= alpha;
            }
        }

        // Pack P hi/lo A-fragments (bf16)
        uint32_t pha[4][4], pla[4][4];
        #pragma unroll
        for (int t = 0; t < 4; t++) {
            split2(s[2 * t][0],     s[2 * t][1],     pha[t][0], pla[t][0]);
            split2(s[2 * t][2],     s[2 * t][3],     pha[t][1], pla[t][1]);
            split2(s[2 * t + 1][0], s[2 * t + 1][1], pha[t][2], pla[t][2]);
            split2(s[2 * t + 1][2], s[2 * t + 1][3], pha[t][3], pla[t][3]);
        }

        // O += P V (V natural in smem; ldmatrix.trans B-frags)
        #pragma unroll
        for (int t = 0; t < 4; t++) {
            uint32_t bvh[8][2], bvl[8][2];
            #pragma unroll
            for (int np = 0; np < 4; np++) {
                const uint32_t adr = kvb + AVH * 2 +
                    ((t * 16 + rA) * AP + np * 16 + kA) * 2;
                LDSM_X4_TRANS(bvh[2 * np][0], bvh[2 * np][1],
                              bvh[2 * np + 1][0], bvh[2 * np + 1][1], adr);
                LDSM_X4_TRANS(bvl[2 * np][0], bvl[2 * np][1],
                              bvl[2 * np + 1][0], bvl[2 * np + 1][1],
                              adr + (AVL - AVH) * 2);
            }
            #pragma unroll
            for (int j = 0; j < 8; j++) {
                MMA_BF16(o[j], pha[t], bvh[j]);
                MMA_BF16(o[j], pha[t], bvl[j]);
                MMA_BF16(o[j], pla[t], bvh[j]);
            }
        }
        __syncthreads();
    }

    // Epilogue: normalize, fp16 hi/lo split, store
    const float inv0 = 1.0f / lrow[0];
    const float inv1 = 1.0f / lrow[1];
    const int row0 = b * 2048 + qt * 128 + wq + gr;
    #pragma unroll
    for (int j = 0; j < 8; j++) {
        const int col = h * 64 + j * 8 + 2 * gc;
        uint32_t h0, l0, h1, l1;
        split2h(o[j][0] * inv0, o[j][1] * inv0, h0, l0);
        split2h(o[j][2] * inv1, o[j][3] * inv1, h1, l1);
        *(uint32_t*)(yh + (size_t)row0 * 1024 + col) = h0;
        *(uint32_t*)(yl + (size_t)row0 * 1024 + col) = l0;
        *(uint32_t*)(yh + (size_t)(row0 + 8) * 1024 + col) = h1;
        *(uint32_t*)(yl + (size_t)(row0 + 8) * 1024 + col) = l1;
    }
}

// ---------------------------------------------------------------------------
// Launch
// ---------------------------------------------------------------------------
extern "C" void kernel_launch(void* const* d_in, const int* in_sizes, int n_in,
                              void* d_out, int out_size)
{
    const float* x      = (const float*)d_in[0];   // [2,2048,1024]
    const float* w_attn = (const float*)d_in[1];   // [1024,3072]
    const float* b_attn = (const float*)d_in[2];   // [3072]
    const float* w_proj = (const float*)d_in[3];   // [1024,1024]
    const float* b_proj = (const float*)d_in[4];   // [1024]
    float* out = (float*)d_out;                    // [2,2048,1024]

    __nv_bfloat16 *qkvh, *qkvl;
    __half *xh, *xl, *wa, *wp, *yh, *yl;
    cudaGetSymbolAddress((void**)&qkvh, g_qkvh);
    cudaGetSymbolAddress((void**)&qkvl, g_qkvl);
    cudaGetSymbolAddress((void**)&xh,  g_xh);
    cudaGetSymbolAddress((void**)&xl,  g_xl);
    cudaGetSymbolAddress((void**)&wa,  g_wa);
    cudaGetSymbolAddress((void**)&wp,  g_wp);
    cudaGetSymbolAddress((void**)&yh,  g_yh);
    cudaGetSymbolAddress((void**)&yl,  g_yl);

    cudaFuncSetAttribute(mma_gemm_kernel,
                         cudaFuncAttributeMaxDynamicSharedMemorySize, 61440);
    cudaFuncSetAttribute(attn_mma_kernel,
                         cudaFuncAttributeMaxDynamicSharedMemorySize, 110592);

    // Pre-pass: split x (fp16 hi/lo), transpose weights to single fp16
    split_fp16_kernel<<<4096, 256>>>(x, xh, xl, 4096 * 1024 / 4);
    transpose_fp16_kernel<<<dim3(3072 / 32, 1024 / 32), dim3(32, 8)>>>(
        w_attn, wa, 1024, 3072);
    transpose_fp16_kernel<<<dim3(1024 / 32, 1024 / 32), dim3(32, 8)>>>(
        w_proj, wp, 1024, 1024);

    // 1) qkv = x @ w_attn + b_attn  (fp16 2-product) -> bf16 hi/lo
    mma_gemm_kernel<<<dim3(4096 / 128, 3072 / 128), 256, 61440>>>(
        xh, xl, wa, b_attn, nullptr, qkvh, qkvl, 4096, 3072, 1024);

    // 2) causal attention (bf16 3-product) -> yh/yl fp16 hi/lo
    attn_mma_kernel<<<dim3(2048 / 128, 16, 2), 256, 110592>>>(qkvh, qkvl, yh, yl);

    // 3) out = y @ w_proj + b_proj  (fp16 2-product, fp32 out)
    mma_gemm_kernel<<<dim3(4096 / 128, 1024 / 128), 256, 61440>>>(
        yh, yl, wp, b_proj, out, nullptr, nullptr, 4096, 1024, 1024);
}

// round 14
// speedup vs baseline: 1.6186x; 1.1786x over previous
#include <cuda_runtime.h>
#include <cuda_bf16.h>
#include <cuda_fp16.h>
#include <cstdint>
#include <math.h>

// Problem constants: B=2, T=2048, C=1024, H=16, D=64, M = B*T = 4096

// ---------------------------------------------------------------------------
// Scratch (allocation forbidden -> device globals)
// ---------------------------------------------------------------------------
__device__ __half g_qkvh[4096 * 3072];            // qkv hi/lo fp16 (attn input)
__device__ __half g_qkvl[4096 * 3072];
__device__ __half g_xh[4096 * 1024];              // x hi/lo fp16
__device__ __half g_xl[4096 * 1024];
__device__ __half g_wa[3072 * 1024];              // w_attn^T fp16  [N,K]
__device__ __half g_wp[1024 * 1024];              // w_proj^T fp16  [N,K]
__device__ __half g_yh[4096 * 1024];              // attention out hi/lo fp16
__device__ __half g_yl[4096 * 1024];

// ---------------------------------------------------------------------------
// PTX helpers (plain sm_100-safe: mma.sync + cp.async + ldmatrix)
// ---------------------------------------------------------------------------
__device__ __forceinline__ uint32_t smem_to_u32(const void* p) {
    uint32_t a;
    asm("{ .reg .u64 t; cvta.to.shared.u64 t, %1; cvt.u32.u64 %0, t; }" : "=r"(a) : "l"(p));
    return a;
}

#define CP_ASYNC16(dst_u32, src_ptr) \
    asm volatile("cp.async.cg.shared.global [%0], [%1], 16;" \
                 :: "r"(dst_u32), "l"(src_ptr) : "memory")
#define CP_COMMIT() asm volatile("cp.async.commit_group;" ::: "memory")
#define CP_WAIT(n)  asm volatile("cp.async.wait_group %0;" :: "n"(n) : "memory")

#define LDSM_X4(r0, r1, r2, r3, addr) \
    asm volatile("ldmatrix.sync.aligned.m8n8.x4.shared.b16 {%0,%1,%2,%3}, [%4];" \
                 : "=r"(r0), "=r"(r1), "=r"(r2), "=r"(r3) : "r"(addr))

#define LDSM_X4_TRANS(r0, r1, r2, r3, addr) \
    asm volatile("ldmatrix.sync.aligned.m8n8.x4.trans.shared.b16 {%0,%1,%2,%3}, [%4];" \
                 : "=r"(r0), "=r"(r1), "=r"(r2), "=r"(r3) : "r"(addr))

#define MMA_FP16(c, a, b) \
    asm volatile("mma.sync.aligned.m16n8k16.row.col.f32.f16.f16.f32 " \
                 "{%0,%1,%2,%3}, {%4,%5,%6,%7}, {%8,%9}, {%0,%1,%2,%3};" \
                 : "+f"((c)[0]), "+f"((c)[1]), "+f"((c)[2]), "+f"((c)[3]) \
                 : "r"((a)[0]), "r"((a)[1]), "r"((a)[2]), "r"((a)[3]), \
                   "r"((b)[0]), "r"((b)[1]))

// fp32 pair -> (hi, lo) fp16x2 packed in u32
__device__ __forceinline__ void split2h(float x, float y, uint32_t& h, uint32_t& l) {
    __half2 h2 = __floats2half2_rn(x, y);
    __half2 l2 = __floats2half2_rn(x - __half2float(__low2half(h2)),
                                   y - __half2float(__high2half(h2)));
    h = *(uint32_t*)&h2;
    l = *(uint32_t*)&l2;
}

// ---------------------------------------------------------------------------
// Pre-pass 1: elementwise fp32 -> (hi, lo) fp16 split
// ---------------------------------------------------------------------------
__global__ __launch_bounds__(256) void split_fp16_kernel(
    const float* __restrict__ in, __half* __restrict__ hi,
    __half* __restrict__ lo, int n4)
{
    int i = blockIdx.x * 256 + threadIdx.x;
    if (i >= n4) return;
    float4 v = ((const float4*)in)[i];
    uint32_t h0, l0, h1, l1;
    split2h(v.x, v.y, h0, l0);
    split2h(v.z, v.w, h1, l1);
    ((uint32_t*)hi)[i * 2 + 0] = h0;
    ((uint32_t*)hi)[i * 2 + 1] = h1;
    ((uint32_t*)lo)[i * 2 + 0] = l0;
    ((uint32_t*)lo)[i * 2 + 1] = l1;
}

// ---------------------------------------------------------------------------
// Pre-pass 2: W[K,N] fp32 -> W^T[N,K] single fp16. 32x32 tiles.
// ---------------------------------------------------------------------------
__global__ __launch_bounds__(256) void transpose_fp16_kernel(
    const float* __restrict__ W, __half* __restrict__ Th, int K, int N)
{
    __shared__ float tile[32][33];
    const int n0 = blockIdx.x * 32;
    const int k0 = blockIdx.y * 32;
    const int tx = threadIdx.x, ty = threadIdx.y;
    #pragma unroll
    for (int j = 0; j < 4; j++) {
        int r = ty + j * 8;
        tile[r][tx] = W[(size_t)(k0 + r) * N + n0 + tx];
    }
    __syncthreads();
    #pragma unroll
    for (int j = 0; j < 4; j++) {
        int r = ty + j * 8;
        Th[(size_t)(n0 + r) * K + k0 + tx] = __float2half_rn(tile[tx][r]);
    }
}

// ---------------------------------------------------------------------------
// Tensor-core GEMM, fp16 2-product: C = Ah@W^T + Al@W^T + bias
// (validated R11 config: 193us QKV, tensor 50.3%)
// ---------------------------------------------------------------------------
#define PITCH 40
#define TILE_H (128 * PITCH)
#define BUF_H  (3 * TILE_H)

__global__ __launch_bounds__(256) void mma_gemm_kernel(
    const __half* __restrict__ Ah, const __half* __restrict__ Al,
    const __half* __restrict__ W,
    const float* __restrict__ bias, float* __restrict__ Cf,
    __half* __restrict__ Ch, __half* __restrict__ Cl,
    int M, int N, int K)
{
    extern __shared__ __align__(16) __half sm[];
    const uint32_t sbase = smem_to_u32(sm);
    const int tid = threadIdx.x;
    const int wid = tid >> 5, lane = tid & 31;
    const int wm = wid & 3;
    const int wn = wid >> 2;
    const int ra = lane >> 2;
    const int c2 = (lane & 3) * 2;
    const int m0 = blockIdx.x * 128;
    const int n0 = blockIdx.y * 128;

    const int r8 = lane & 7;
    const int s0 = (lane >> 3) & 1;
    const int s1 = (lane >> 4) & 1;
    const int rA = r8 + s0 * 8, kA = s1 * 8;
    const int rB = r8 + s1 * 8, kB = s0 * 8;

    const __half* srcs[3] = {
        Ah + (size_t)m0 * K, Al + (size_t)m0 * K, W + (size_t)n0 * K
    };

    float acc[2][8][4];
    #pragma unroll
    for (int mi = 0; mi < 2; mi++)
        #pragma unroll
        for (int ni = 0; ni < 8; ni++)
            #pragma unroll
            for (int q = 0; q < 4; q++) acc[mi][ni][q] = 0.f;

    const int NCH = K >> 5;

    auto issue_chunk = [&](int ch, int buf) {
        const int k0 = ch * 32;
        #pragma unroll
        for (int t = 0; t < 3; t++) {
            const __half* src0 = srcs[t] + k0;
            const uint32_t dst0 = sbase + (buf * BUF_H + t * TILE_H) * 2;
            #pragma unroll
            for (int i = 0; i < 2; i++) {
                int idx = tid + i * 256;
                int row = idx >> 2, seg = idx & 3;
                CP_ASYNC16(dst0 + (row * PITCH + seg * 8) * 2,
                           src0 + (size_t)row * K + seg * 8);
            }
        }
    };

    issue_chunk(0, 0);
    CP_COMMIT();

    for (int ch = 0; ch < NCH; ch++) {
        const int buf = ch & 1;
        if (ch + 1 < NCH) {
            issue_chunk(ch + 1, buf ^ 1);
            CP_COMMIT();
            CP_WAIT(1);
        } else {
            CP_WAIT(0);
        }
        __syncthreads();

        const uint32_t boff = sbase + buf * BUF_H * 2;
        #pragma unroll
        for (int ks = 0; ks < 2; ks++) {
            uint32_t ah[2][4], al[2][4], bw[8][2];
            #pragma unroll
            for (int mi = 0; mi < 2; mi++) {
                const int row = wm * 32 + mi * 16 + rA;
                const uint32_t adr = boff + (row * PITCH + ks * 16 + kA) * 2;
                LDSM_X4(ah[mi][0], ah[mi][1], ah[mi][2], ah[mi][3], adr);
                LDSM_X4(al[mi][0], al[mi][1], al[mi][2], al[mi][3],
                        adr + TILE_H * 2);
            }
            #pragma unroll
            for (int np = 0; np < 4; np++) {
                const int row = wn * 64 + np * 16 + rB;
                const uint32_t adr = boff + 2 * TILE_H * 2 +
                                     (row * PITCH + ks * 16 + kB) * 2;
                LDSM_X4(bw[2 * np][0], bw[2 * np][1],
                        bw[2 * np + 1][0], bw[2 * np + 1][1], adr);
            }
            #pragma unroll
            for (int mi = 0; mi < 2; mi++)
                #pragma unroll
                for (int ni = 0; ni < 8; ni++) {
                    MMA_FP16(acc[mi][ni], ah[mi], bw[ni]);
                    MMA_FP16(acc[mi][ni], al[mi], bw[ni]);
                }
        }
        __syncthreads();
    }

    // Epilogue
    #pragma unroll
    for (int ni = 0; ni < 8; ni++) {
        const int col = n0 + wn * 64 + ni * 8 + c2;
        const float bv0 = bias[col], bv1 = bias[col + 1];
        #pragma unroll
        for (int mi = 0; mi < 2; mi++) {
            const int r0 = m0 + wm * 32 + mi * 16 + ra;
            const float v00 = acc[mi][ni][0] + bv0, v01 = acc[mi][ni][1] + bv1;
            const float v10 = acc[mi][ni][2] + bv0, v11 = acc[mi][ni][3] + bv1;
            if (Ch) {
                uint32_t h0, l0, h1, l1;
                split2h(v00, v01, h0, l0);
                split2h(v10, v11, h1, l1);
                *(uint32_t*)(Ch + (size_t)r0 * N + col) = h0;
                *(uint32_t*)(Cl + (size_t)r0 * N + col) = l0;
                *(uint32_t*)(Ch + (size_t)(r0 + 8) * N + col) = h1;
                *(uint32_t*)(Cl + (size_t)(r0 + 8) * N + col) = l1;
            } else {
                *(float2*)(Cf + (size_t)r0 * N + col) = make_float2(v00, v01);
                *(float2*)(Cf + (size_t)(r0 + 8) * N + col) = make_float2(v10, v11);
            }
        }
    }
}

// ---------------------------------------------------------------------------
// Tensor-core causal flash attention, fp16 2-product everywhere:
//   S = (Qh + Ql) @ Kh^T     (K single fp16 = hi plane)
//   O += (Ph + Pl) @ Vh      (V single fp16 = hi plane)
// 8 warps x 16 q-rows, CTA 128 x 64-keys, cp.async K/V double buffer.
// smem (fp16, pitch 72): Qh[128] Ql[128] @ 0/9216;
//   KV buffers @ 18432 + buf*9216: Kh[64] @ +0, Vh[64] @ +4608.
// Total 36864 halfs = 73728 B -> 2 CTAs/SM.
// ---------------------------------------------------------------------------
#define AP 72
#define AQH 0
#define AQL 9216
#define AKV0 18432
#define AKVSTRIDE 9216
#define AKH 0
#define AVH 4608

__global__ __launch_bounds__(256) void attn_mma_kernel(
    const __half* __restrict__ qh, const __half* __restrict__ ql,
    __half* __restrict__ yh, __half* __restrict__ yl)
{
    extern __shared__ __align__(16) __half sma[];
    const uint32_t sbase = smem_to_u32(sma);
    const int tid = threadIdx.x;
    const int wid = tid >> 5, lane = tid & 31;
    const int gr = lane >> 2;
    const int gc = lane & 3;
    const int qt = gridDim.x - 1 - blockIdx.x;    // heavy CTAs first
    const int h  = blockIdx.y;
    const int b  = blockIdx.z;
    const int wq = wid * 16;

    const int r8 = lane & 7;
    const int s0 = (lane >> 3) & 1;
    const int s1 = (lane >> 4) & 1;
    const int rA = r8 + s0 * 8, kA = s1 * 8;
    const int rB = r8 + s1 * 8, kB = s0 * 8;

    const float SSCALE = 0.125f * 1.44269504088896f;  // 1/sqrt(64)*log2(e)

    const size_t kcol = (size_t)(b * 2048) * 3072 + 1024 + h * 64;
    const size_t vcol = kcol + 1024;

    // cp.async one K/V tile pair (hi planes only) for key-tile kt
    auto issue_kv = [&](int kt, int buf) {
        const uint32_t bb = sbase + (AKV0 + buf * AKVSTRIDE) * 2;
        #pragma unroll
        for (int i = 0; i < 2; i++) {
            int f = tid + i * 256;                // 0..511
            int j = f >> 3, seg = f & 7;
            const size_t off = (size_t)(kt * 64 + j) * 3072 + seg * 8;
            const uint32_t d = (j * AP + seg * 8) * 2;
            CP_ASYNC16(bb + AKH * 2 + d, qh + kcol + off);
            CP_ASYNC16(bb + AVH * 2 + d, qh + vcol + off);
        }
    };

    // Load Q tile (128 x 64 fp16 hi/lo)
    {
        const size_t qrow = (size_t)(b * 2048 + qt * 128) * 3072 + h * 64;
        #pragma unroll
        for (int i = 0; i < 4; i++) {
            int f = tid + i * 256;                // 0..1023
            int r = f >> 3, seg = f & 7;
            const size_t off = qrow + (size_t)r * 3072 + seg * 8;
            *(uint4*)&sma[AQH + r * AP + seg * 8] = *(const uint4*)(qh + off);
            *(uint4*)&sma[AQL + r * AP + seg * 8] = *(const uint4*)(ql + off);
        }
    }

    float o[8][4];
    #pragma unroll
    for (int j = 0; j < 8; j++)
        #pragma unroll
        for (int q = 0; q < 4; q++) o[j][q] = 0.f;
    float mrow[2] = {-1e30f, -1e30f};
    float lrow[2] = {0.f, 0.f};

    const int kt_max = 2 * qt + 1;

    issue_kv(0, 0);
    CP_COMMIT();

    for (int kt = 0; kt <= kt_max; kt++) {
        const int buf = kt & 1;
        if (kt < kt_max) {
            issue_kv(kt + 1, buf ^ 1);
            CP_COMMIT();
            CP_WAIT(1);
        } else {
            CP_WAIT(0);
        }
        __syncthreads();

        const uint32_t kvb = sbase + (AKV0 + buf * AKVSTRIDE) * 2;

        // S = Q K^T (16x64 per warp), fp16 2-product
        float s[8][4];
        #pragma unroll
        for (int j = 0; j < 8; j++)
            #pragma unroll
            for (int q = 0; q < 4; q++) s[j][q] = 0.f;

        #pragma unroll
        for (int ks = 0; ks < 4; ks++) {
            uint32_t ah[4], al[4], bk[8][2];
            {
                const uint32_t adr = sbase +
                    (AQH + (wq + rA) * AP + ks * 16 + kA) * 2;
                LDSM_X4(ah[0], ah[1], ah[2], ah[3], adr);
                LDSM_X4(al[0], al[1], al[2], al[3], adr + (AQL - AQH) * 2);
            }
            #pragma unroll
            for (int np = 0; np < 4; np++) {
                const uint32_t adr = kvb + AKH * 2 +
                    ((np * 16 + rB) * AP + ks * 16 + kB) * 2;
                LDSM_X4(bk[2 * np][0], bk[2 * np][1],
                        bk[2 * np + 1][0], bk[2 * np + 1][1], adr);
            }
            #pragma unroll
            for (int j = 0; j < 8; j++) {
                MMA_FP16(s[j], ah, bk[j]);
                MMA_FP16(s[j], al, bk[j]);
            }
        }

        // Scale + causal mask
        #pragma unroll
        for (int j = 0; j < 8; j++)
            #pragma unroll
            for (int q = 0; q < 4; q++) s[j][q] *= SSCALE;

        if (kt >= 2 * qt) {
            const int row0 = qt * 128 + wq + gr;
            #pragma unroll
            for (int j = 0; j < 8; j++) {
                const int col = kt * 64 + j * 8 + 2 * gc;
                if (col > row0)         s[j][0] = -1e30f;
                if (col + 1 > row0)     s[j][1] = -1e30f;
                if (col > row0 + 8)     s[j][2] = -1e30f;
                if (col + 1 > row0 + 8) s[j][3] = -1e30f;
            }
        }

        // Online softmax
        #pragma unroll
        for (int i = 0; i < 2; i++) {
            const int q0i = i * 2;
            float mx = -1e30f;
            #pragma unroll
            for (int j = 0; j < 8; j++)
                mx = fmaxf(mx, fmaxf(s[j][q0i], s[j][q0i + 1]));
            mx = fmaxf(mx, __shfl_xor_sync(0xffffffffu, mx, 1));
            mx = fmaxf(mx, __shfl_xor_sync(0xffffffffu, mx, 2));
            const float mnew = fmaxf(mrow[i], mx);
            const float alpha = exp2f(mrow[i] - mnew);
            float rsum = 0.f;
            #pragma unroll
            for (int j = 0; j < 8; j++) {
                s[j][q0i]     = exp2f(s[j][q0i] - mnew);
                s[j][q0i + 1] = exp2f(s[j][q0i + 1] - mnew);
                rsum += s[j][q0i] + s[j][q0i + 1];
            }
            rsum += __shfl_xor_sync(0xffffffffu, rsum, 1);
            rsum += __shfl_xor_sync(0xffffffffu, rsum, 2);
            lrow[i] = lrow[i] * alpha + rsum;
            mrow[i] = mnew;
            #pragma unroll
            for (int j = 0; j < 8; j++) {
                o[j][q0i]     *= alpha;
                o[j][q0i + 1] *= alpha;
            }
        }

        // Pack P hi/lo fp16 A-fragments
        uint32_t pha[4][4], pla[4][4];
        #pragma unroll
        for (int t = 0; t < 4; t++) {
            split2h(s[2 * t][0],     s[2 * t][1],     pha[t][0], pla[t][0]);
            split2h(s[2 * t][2],     s[2 * t][3],     pha[t][1], pla[t][1]);
            split2h(s[2 * t + 1][0], s[2 * t + 1][1], pha[t][2], pla[t][2]);
            split2h(s[2 * t + 1][2], s[2 * t + 1][3], pha[t][3], pla[t][3]);
        }

        // O += P V (V natural hi-plane in smem; ldmatrix.trans B-frags)
        #pragma unroll
        for (int t = 0; t < 4; t++) {
            uint32_t bv[8][2];
            #pragma unroll
            for (int np = 0; np < 4; np++) {
                const uint32_t adr = kvb + AVH * 2 +
                    ((t * 16 + rA) * AP + np * 16 + kA) * 2;
                LDSM_X4_TRANS(bv[2 * np][0], bv[2 * np][1],
                              bv[2 * np + 1][0], bv[2 * np + 1][1], adr);
            }
            #pragma unroll
            for (int j = 0; j < 8; j++) {
                MMA_FP16(o[j], pha[t], bv[j]);
                MMA_FP16(o[j], pla[t], bv[j]);
            }
        }
        __syncthreads();
    }

    // Epilogue: normalize, fp16 hi/lo split, store
    const float inv0 = 1.0f / lrow[0];
    const float inv1 = 1.0f / lrow[1];
    const int row0 = b * 2048 + qt * 128 + wq + gr;
    #pragma unroll
    for (int j = 0; j < 8; j++) {
        const int col = h * 64 + j * 8 + 2 * gc;
        uint32_t h0, l0, h1, l1;
        split2h(o[j][0] * inv0, o[j][1] * inv0, h0, l0);
        split2h(o[j][2] * inv1, o[j][3] * inv1, h1, l1);
        *(uint32_t*)(yh + (size_t)row0 * 1024 + col) = h0;
        *(uint32_t*)(yl + (size_t)row0 * 1024 + col) = l0;
        *(uint32_t*)(yh + (size_t)(row0 + 8) * 1024 + col) = h1;
        *(uint32_t*)(yl + (size_t)(row0 + 8) * 1024 + col) = l1;
    }
}

// ---------------------------------------------------------------------------
// Launch
// ---------------------------------------------------------------------------
extern "C" void kernel_launch(void* const* d_in, const int* in_sizes, int n_in,
                              void* d_out, int out_size)
{
    const float* x      = (const float*)d_in[0];   // [2,2048,1024]
    const float* w_attn = (const float*)d_in[1];   // [1024,3072]
    const float* b_attn = (const float*)d_in[2];   // [3072]
    const float* w_proj = (const float*)d_in[3];   // [1024,1024]
    const float* b_proj = (const float*)d_in[4];   // [1024]
    float* out = (float*)d_out;                    // [2,2048,1024]

    __half *qkvh, *qkvl, *xh, *xl, *wa, *wp, *yh, *yl;
    cudaGetSymbolAddress((void**)&qkvh, g_qkvh);
    cudaGetSymbolAddress((void**)&qkvl, g_qkvl);
    cudaGetSymbolAddress((void**)&xh,  g_xh);
    cudaGetSymbolAddress((void**)&xl,  g_xl);
    cudaGetSymbolAddress((void**)&wa,  g_wa);
    cudaGetSymbolAddress((void**)&wp,  g_wp);
    cudaGetSymbolAddress((void**)&yh,  g_yh);
    cudaGetSymbolAddress((void**)&yl,  g_yl);

    cudaFuncSetAttribute(mma_gemm_kernel,
                         cudaFuncAttributeMaxDynamicSharedMemorySize, 61440);
    cudaFuncSetAttribute(attn_mma_kernel,
                         cudaFuncAttributeMaxDynamicSharedMemorySize, 73728);

    // Pre-pass: split x (fp16 hi/lo), transpose weights to single fp16
    split_fp16_kernel<<<4096, 256>>>(x, xh, xl, 4096 * 1024 / 4);
    transpose_fp16_kernel<<<dim3(3072 / 32, 1024 / 32), dim3(32, 8)>>>(
        w_attn, wa, 1024, 3072);
    transpose_fp16_kernel<<<dim3(1024 / 32, 1024 / 32), dim3(32, 8)>>>(
        w_proj, wp, 1024, 1024);

    // 1) qkv = x @ w_attn + b_attn  (fp16 2-product) -> fp16 hi/lo
    mma_gemm_kernel<<<dim3(4096 / 128, 3072 / 128), 256, 61440>>>(
        xh, xl, wa, b_attn, nullptr, qkvh, qkvl, 4096, 3072, 1024);

    // 2) causal attention (fp16 2-product) -> yh/yl fp16 hi/lo
    attn_mma_kernel<<<dim3(2048 / 128, 16, 2), 256, 73728>>>(qkvh, qkvl, yh, yl);

    // 3) out = y @ w_proj + b_proj  (fp16 2-product, fp32 out)
    mma_gemm_kernel<<<dim3(4096 / 128, 1024 / 128), 256, 61440>>>(
        yh, yl, wp, b_proj, out, nullptr, nullptr, 4096, 1024, 1024);
}

// round 15
// speedup vs baseline: 1.6974x; 1.0486x over previous
#include <cuda_runtime.h>
#include <cuda_fp16.h>
#include <cstdint>
#include <math.h>

// Problem constants: B=2, T=2048, C=1024, H=16, D=64, M = B*T = 4096

// ---------------------------------------------------------------------------
// Scratch (allocation forbidden -> device globals)
// ---------------------------------------------------------------------------
__device__ __half g_qkvh[4096 * 3072];            // qkv hi fp16
__device__ __half g_qkvl[4096 * 3072];            // qkv lo fp16 (only Q cols used)
__device__ __half g_xh[4096 * 1024];              // x hi/lo fp16
__device__ __half g_xl[4096 * 1024];
__device__ __half g_wa[3072 * 1024];              // w_attn^T fp16  [N,K]
__device__ __half g_wp[1024 * 1024];              // w_proj^T fp16  [N,K]
__device__ __half g_yh[4096 * 1024];              // attention out fp16 (single)

// ---------------------------------------------------------------------------
// PTX helpers (plain sm_100-safe: mma.sync + cp.async + ldmatrix)
// ---------------------------------------------------------------------------
__device__ __forceinline__ uint32_t smem_to_u32(const void* p) {
    uint32_t a;
    asm("{ .reg .u64 t; cvta.to.shared.u64 t, %1; cvt.u32.u64 %0, t; }" : "=r"(a) : "l"(p));
    return a;
}

#define CP_ASYNC16(dst_u32, src_ptr) \
    asm volatile("cp.async.cg.shared.global [%0], [%1], 16;" \
                 :: "r"(dst_u32), "l"(src_ptr) : "memory")
#define CP_COMMIT() asm volatile("cp.async.commit_group;" ::: "memory")
#define CP_WAIT1()  asm volatile("cp.async.wait_group 1;" ::: "memory")
#define CP_WAIT0()  asm volatile("cp.async.wait_group 0;" ::: "memory")

#define LDSM_X4(r0, r1, r2, r3, addr) \
    asm volatile("ldmatrix.sync.aligned.m8n8.x4.shared.b16 {%0,%1,%2,%3}, [%4];" \
                 : "=r"(r0), "=r"(r1), "=r"(r2), "=r"(r3) : "r"(addr))

#define LDSM_X4_TRANS(r0, r1, r2, r3, addr) \
    asm volatile("ldmatrix.sync.aligned.m8n8.x4.trans.shared.b16 {%0,%1,%2,%3}, [%4];" \
                 : "=r"(r0), "=r"(r1), "=r"(r2), "=r"(r3) : "r"(addr))

#define MMA_FP16(c, a, b) \
    asm volatile("mma.sync.aligned.m16n8k16.row.col.f32.f16.f16.f32 " \
                 "{%0,%1,%2,%3}, {%4,%5,%6,%7}, {%8,%9}, {%0,%1,%2,%3};" \
                 : "+f"((c)[0]), "+f"((c)[1]), "+f"((c)[2]), "+f"((c)[3]) \
                 : "r"((a)[0]), "r"((a)[1]), "r"((a)[2]), "r"((a)[3]), \
                   "r"((b)[0]), "r"((b)[1]))

// fp32 pair -> (hi, lo) fp16x2 packed in u32
__device__ __forceinline__ void split2h(float x, float y, uint32_t& h, uint32_t& l) {
    __half2 h2 = __floats2half2_rn(x, y);
    __half2 l2 = __floats2half2_rn(x - __half2float(__low2half(h2)),
                                   y - __half2float(__high2half(h2)));
    h = *(uint32_t*)&h2;
    l = *(uint32_t*)&l2;
}
__device__ __forceinline__ uint32_t pack2h(float x, float y) {
    __half2 h2 = __floats2half2_rn(x, y);
    return *(uint32_t*)&h2;
}

// ---------------------------------------------------------------------------
// Pre-pass 1: elementwise fp32 -> (hi, lo) fp16 split
// ---------------------------------------------------------------------------
__global__ __launch_bounds__(256) void split_fp16_kernel(
    const float* __restrict__ in, __half* __restrict__ hi,
    __half* __restrict__ lo, int n4)
{
    int i = blockIdx.x * 256 + threadIdx.x;
    if (i >= n4) return;
    float4 v = ((const float4*)in)[i];
    uint32_t h0, l0, h1, l1;
    split2h(v.x, v.y, h0, l0);
    split2h(v.z, v.w, h1, l1);
    ((uint32_t*)hi)[i * 2 + 0] = h0;
    ((uint32_t*)hi)[i * 2 + 1] = h1;
    ((uint32_t*)lo)[i * 2 + 0] = l0;
    ((uint32_t*)lo)[i * 2 + 1] = l1;
}

// ---------------------------------------------------------------------------
// Pre-pass 2: W[K,N] fp32 -> W^T[N,K] single fp16. 32x32 tiles.
// ---------------------------------------------------------------------------
__global__ __launch_bounds__(256) void transpose_fp16_kernel(
    const float* __restrict__ W, __half* __restrict__ Th, int K, int N)
{
    __shared__ float tile[32][33];
    const int n0 = blockIdx.x * 32;
    const int k0 = blockIdx.y * 32;
    const int tx = threadIdx.x, ty = threadIdx.y;
    #pragma unroll
    for (int j = 0; j < 4; j++) {
        int r = ty + j * 8;
        tile[r][tx] = W[(size_t)(k0 + r) * N + n0 + tx];
    }
    __syncthreads();
    #pragma unroll
    for (int j = 0; j < 4; j++) {
        int r = ty + j * 8;
        Th[(size_t)(n0 + r) * K + k0 + tx] = __float2half_rn(tile[tx][r]);
    }
}

// ---------------------------------------------------------------------------
// Tensor-core GEMM, fp16: C = (Ah [+ Al]) @ W^T + bias
// Al == nullptr -> single-product. 3-stage cp.async, 1 barrier/chunk.
// 8 warps, 32x64 warp tiles, CTA 128x128, K-chunk 32.
// smem: 3 stages x 3 tiles x 128x40 fp16 = 92160 B.
// ---------------------------------------------------------------------------
#define PITCH 40
#define TILE_H (128 * PITCH)
#define STG_H  (3 * TILE_H)

__global__ __launch_bounds__(256) void mma_gemm_kernel(
    const __half* __restrict__ Ah, const __half* __restrict__ Al,
    const __half* __restrict__ W,
    const float* __restrict__ bias, float* __restrict__ Cf,
    __half* __restrict__ Ch, __half* __restrict__ Cl, int lo_cols,
    int M, int N, int K)
{
    extern __shared__ __align__(16) __half sm[];
    const uint32_t sbase = smem_to_u32(sm);
    const int tid = threadIdx.x;
    const int wid = tid >> 5, lane = tid & 31;
    const int wm = wid & 3;
    const int wn = wid >> 2;
    const int ra = lane >> 2;
    const int c2 = (lane & 3) * 2;
    const int m0 = blockIdx.x * 128;
    const int n0 = blockIdx.y * 128;
    const bool twoProd = (Al != nullptr);

    const int r8 = lane & 7;
    const int s0 = (lane >> 3) & 1;
    const int s1 = (lane >> 4) & 1;
    const int rA = r8 + s0 * 8, kA = s1 * 8;
    const int rB = r8 + s1 * 8, kB = s0 * 8;

    const __half* srcA = Ah + (size_t)m0 * K;
    const __half* srcL = twoProd ? (Al + (size_t)m0 * K) : nullptr;
    const __half* srcW = W + (size_t)n0 * K;

    float acc[2][8][4];
    #pragma unroll
    for (int mi = 0; mi < 2; mi++)
        #pragma unroll
        for (int ni = 0; ni < 8; ni++)
            #pragma unroll
            for (int q = 0; q < 4; q++) acc[mi][ni][q] = 0.f;

    const int NCH = K >> 5;

    auto issue_chunk = [&](int ch, int stg) {
        const int k0 = ch * 32;
        const uint32_t sb = sbase + stg * STG_H * 2;
        #pragma unroll
        for (int i = 0; i < 2; i++) {
            int idx = tid + i * 256;
            int row = idx >> 2, seg = idx & 3;
            const uint32_t d = (row * PITCH + seg * 8) * 2;
            const size_t go = (size_t)row * K + k0 + seg * 8;
            CP_ASYNC16(sb + d, srcA + go);
            if (twoProd) CP_ASYNC16(sb + TILE_H * 2 + d, srcL + go);
            CP_ASYNC16(sb + 2 * TILE_H * 2 + d, srcW + go);
        }
    };

    issue_chunk(0, 0);
    CP_COMMIT();
    issue_chunk(1, 1);
    CP_COMMIT();

    for (int ch = 0; ch < NCH; ch++) {
        const int stg = ch % 3;
        if (ch + 1 < NCH) CP_WAIT1(); else CP_WAIT0();
        __syncthreads();
        if (ch + 2 < NCH) {
            issue_chunk(ch + 2, (ch + 2) % 3);
            CP_COMMIT();
        }

        const uint32_t boff = sbase + stg * STG_H * 2;
        #pragma unroll
        for (int ks = 0; ks < 2; ks++) {
            uint32_t ah[2][4], al[2][4], bw[8][2];
            #pragma unroll
            for (int mi = 0; mi < 2; mi++) {
                const int row = wm * 32 + mi * 16 + rA;
                const uint32_t adr = boff + (row * PITCH + ks * 16 + kA) * 2;
                LDSM_X4(ah[mi][0], ah[mi][1], ah[mi][2], ah[mi][3], adr);
                if (twoProd)
                    LDSM_X4(al[mi][0], al[mi][1], al[mi][2], al[mi][3],
                            adr + TILE_H * 2);
            }
            #pragma unroll
            for (int np = 0; np < 4; np++) {
                const int row = wn * 64 + np * 16 + rB;
                const uint32_t adr = boff + 2 * TILE_H * 2 +
                                     (row * PITCH + ks * 16 + kB) * 2;
                LDSM_X4(bw[2 * np][0], bw[2 * np][1],
                        bw[2 * np + 1][0], bw[2 * np + 1][1], adr);
            }
            #pragma unroll
            for (int mi = 0; mi < 2; mi++)
                #pragma unroll
                for (int ni = 0; ni < 8; ni++) {
                    MMA_FP16(acc[mi][ni], ah[mi], bw[ni]);
                    if (twoProd) MMA_FP16(acc[mi][ni], al[mi], bw[ni]);
                }
        }
        // single barrier per chunk (3-stage makes trailing barrier unnecessary)
    }

    // Epilogue
    #pragma unroll
    for (int ni = 0; ni < 8; ni++) {
        const int col = n0 + wn * 64 + ni * 8 + c2;
        const float bv0 = bias[col], bv1 = bias[col + 1];
        #pragma unroll
        for (int mi = 0; mi < 2; mi++) {
            const int r0 = m0 + wm * 32 + mi * 16 + ra;
            const float v00 = acc[mi][ni][0] + bv0, v01 = acc[mi][ni][1] + bv1;
            const float v10 = acc[mi][ni][2] + bv0, v11 = acc[mi][ni][3] + bv1;
            if (Ch) {
                if (col < lo_cols) {
                    uint32_t h0, l0, h1, l1;
                    split2h(v00, v01, h0, l0);
                    split2h(v10, v11, h1, l1);
                    *(uint32_t*)(Ch + (size_t)r0 * N + col) = h0;
                    *(uint32_t*)(Cl + (size_t)r0 * N + col) = l0;
                    *(uint32_t*)(Ch + (size_t)(r0 + 8) * N + col) = h1;
                    *(uint32_t*)(Cl + (size_t)(r0 + 8) * N + col) = l1;
                } else {
                    *(uint32_t*)(Ch + (size_t)r0 * N + col) = pack2h(v00, v01);
                    *(uint32_t*)(Ch + (size_t)(r0 + 8) * N + col) = pack2h(v10, v11);
                }
            } else {
                *(float2*)(Cf + (size_t)r0 * N + col) = make_float2(v00, v01);
                *(float2*)(Cf + (size_t)(r0 + 8) * N + col) = make_float2(v10, v11);
            }
        }
    }
}

// ---------------------------------------------------------------------------
// Tensor-core causal flash attention, fp16 2-product S / 2-product PV,
// K/V single fp16 (hi plane). 3-stage cp.async KV pipeline, 1 barrier/kt.
// 8 warps x 16 q-rows, CTA 128 x 64-keys.
// smem (fp16, pitch 72): Qh[128] Ql[128] @ 0/9216;
//   KV stages @ 18432 + stg*9216: Kh[64] @ +0, Vh[64] @ +4608.
// Total 46080 halfs = 92160 B -> 2 CTAs/SM.
// Output: yh single fp16.
// ---------------------------------------------------------------------------
#define AP 72
#define AQH 0
#define AQL 9216
#define AKV0 18432
#define AKVSTRIDE 9216
#define AKH 0
#define AVH 4608

__global__ __launch_bounds__(256) void attn_mma_kernel(
    const __half* __restrict__ qh, const __half* __restrict__ ql,
    __half* __restrict__ yh)
{
    extern __shared__ __align__(16) __half sma[];
    const uint32_t sbase = smem_to_u32(sma);
    const int tid = threadIdx.x;
    const int wid = tid >> 5, lane = tid & 31;
    const int gr = lane >> 2;
    const int gc = lane & 3;
    const int qt = gridDim.x - 1 - blockIdx.x;    // heavy CTAs first
    const int h  = blockIdx.y;
    const int b  = blockIdx.z;
    const int wq = wid * 16;

    const int r8 = lane & 7;
    const int s0 = (lane >> 3) & 1;
    const int s1 = (lane >> 4) & 1;
    const int rA = r8 + s0 * 8, kA = s1 * 8;
    const int rB = r8 + s1 * 8, kB = s0 * 8;

    const float SSCALE = 0.125f * 1.44269504088896f;  // 1/sqrt(64)*log2(e)

    const size_t kcol = (size_t)(b * 2048) * 3072 + 1024 + h * 64;
    const size_t vcol = kcol + 1024;

    auto issue_kv = [&](int kt, int stg) {
        const uint32_t bb = sbase + (AKV0 + stg * AKVSTRIDE) * 2;
        #pragma unroll
        for (int i = 0; i < 2; i++) {
            int f = tid + i * 256;                // 0..511
            int j = f >> 3, seg = f & 7;
            const size_t off = (size_t)(kt * 64 + j) * 3072 + seg * 8;
            const uint32_t d = (j * AP + seg * 8) * 2;
            CP_ASYNC16(bb + AKH * 2 + d, qh + kcol + off);
            CP_ASYNC16(bb + AVH * 2 + d, qh + vcol + off);
        }
    };

    // Load Q tile (128 x 64 fp16 hi/lo)
    {
        const size_t qrow = (size_t)(b * 2048 + qt * 128) * 3072 + h * 64;
        #pragma unroll
        for (int i = 0; i < 4; i++) {
            int f = tid + i * 256;                // 0..1023
            int r = f >> 3, seg = f & 7;
            const size_t off = qrow + (size_t)r * 3072 + seg * 8;
            *(uint4*)&sma[AQH + r * AP + seg * 8] = *(const uint4*)(qh + off);
            *(uint4*)&sma[AQL + r * AP + seg * 8] = *(const uint4*)(ql + off);
        }
    }

    float o[8][4];
    #pragma unroll
    for (int j = 0; j < 8; j++)
        #pragma unroll
        for (int q = 0; q < 4; q++) o[j][q] = 0.f;
    float mrow[2] = {-1e30f, -1e30f};
    float lrow[2] = {0.f, 0.f};

    const int kt_max = 2 * qt + 1;

    issue_kv(0, 0);
    CP_COMMIT();
    if (kt_max >= 1) {
        issue_kv(1, 1);
        CP_COMMIT();
    }

    for (int kt = 0; kt <= kt_max; kt++) {
        const int stg = kt % 3;
        if (kt < kt_max) CP_WAIT1(); else CP_WAIT0();
        __syncthreads();
        if (kt + 2 <= kt_max) {
            issue_kv(kt + 2, (kt + 2) % 3);
            CP_COMMIT();
        }

        const uint32_t kvb = sbase + (AKV0 + stg * AKVSTRIDE) * 2;

        // S = Q K^T (16x64 per warp), fp16 2-product
        float s[8][4];
        #pragma unroll
        for (int j = 0; j < 8; j++)
            #pragma unroll
            for (int q = 0; q < 4; q++) s[j][q] = 0.f;

        #pragma unroll
        for (int ks = 0; ks < 4; ks++) {
            uint32_t ah[4], al[4], bk[8][2];
            {
                const uint32_t adr = sbase +
                    (AQH + (wq + rA) * AP + ks * 16 + kA) * 2;
                LDSM_X4(ah[0], ah[1], ah[2], ah[3], adr);
                LDSM_X4(al[0], al[1], al[2], al[3], adr + (AQL - AQH) * 2);
            }
            #pragma unroll
            for (int np = 0; np < 4; np++) {
                const uint32_t adr = kvb + AKH * 2 +
                    ((np * 16 + rB) * AP + ks * 16 + kB) * 2;
                LDSM_X4(bk[2 * np][0], bk[2 * np][1],
                        bk[2 * np + 1][0], bk[2 * np + 1][1], adr);
            }
            #pragma unroll
            for (int j = 0; j < 8; j++) {
                MMA_FP16(s[j], ah, bk[j]);
                MMA_FP16(s[j], al, bk[j]);
            }
        }

        // Scale + causal mask
        #pragma unroll
        for (int j = 0; j < 8; j++)
            #pragma unroll
            for (int q = 0; q < 4; q++) s[j][q] *= SSCALE;

        if (kt >= 2 * qt) {
            const int row0 = qt * 128 + wq + gr;
            #pragma unroll
            for (int j = 0; j < 8; j++) {
                const int col = kt * 64 + j * 8 + 2 * gc;
                if (col > row0)         s[j][0] = -1e30f;
                if (col + 1 > row0)     s[j][1] = -1e30f;
                if (col > row0 + 8)     s[j][2] = -1e30f;
                if (col + 1 > row0 + 8) s[j][3] = -1e30f;
            }
        }

        // Online softmax
        #pragma unroll
        for (int i = 0; i < 2; i++) {
            const int q0i = i * 2;
            float mx = -1e30f;
            #pragma unroll
            for (int j = 0; j < 8; j++)
                mx = fmaxf(mx, fmaxf(s[j][q0i], s[j][q0i + 1]));
            mx = fmaxf(mx, __shfl_xor_sync(0xffffffffu, mx, 1));
            mx = fmaxf(mx, __shfl_xor_sync(0xffffffffu, mx, 2));
            const float mnew = fmaxf(mrow[i], mx);
            const float alpha = exp2f(mrow[i] - mnew);
            float rsum = 0.f;
            #pragma unroll
            for (int j = 0; j < 8; j++) {
                s[j][q0i]     = exp2f(s[j][q0i] - mnew);
                s[j][q0i + 1] = exp2f(s[j][q0i + 1] - mnew);
                rsum += s[j][q0i] + s[j][q0i + 1];
            }
            rsum += __shfl_xor_sync(0xffffffffu, rsum, 1);
            rsum += __shfl_xor_sync(0xffffffffu, rsum, 2);
            lrow[i] = lrow[i] * alpha + rsum;
            mrow[i] = mnew;
            #pragma unroll
            for (int j = 0; j < 8; j++) {
                o[j][q0i]     *= alpha;
                o[j][q0i + 1] *= alpha;
            }
        }

        // Pack P hi/lo fp16 A-fragments
        uint32_t pha[4][4], pla[4][4];
        #pragma unroll
        for (int t = 0; t < 4; t++) {
            split2h(s[2 * t][0],     s[2 * t][1],     pha[t][0], pla[t][0]);
            split2h(s[2 * t][2],     s[2 * t][3],     pha[t][1], pla[t][1]);
            split2h(s[2 * t + 1][0], s[2 * t + 1][1], pha[t][2], pla[t][2]);
            split2h(s[2 * t + 1][2], s[2 * t + 1][3], pha[t][3], pla[t][3]);
        }

        // O += P V (V natural hi-plane in smem; ldmatrix.trans B-frags)
        #pragma unroll
        for (int t = 0; t < 4; t++) {
            uint32_t bv[8][2];
            #pragma unroll
            for (int np = 0; np < 4; np++) {
                const uint32_t adr = kvb + AVH * 2 +
                    ((t * 16 + rA) * AP + np * 16 + kA) * 2;
                LDSM_X4_TRANS(bv[2 * np][0], bv[2 * np][1],
                              bv[2 * np + 1][0], bv[2 * np + 1][1], adr);
            }
            #pragma unroll
            for (int j = 0; j < 8; j++) {
                MMA_FP16(o[j], pha[t], bv[j]);
                MMA_FP16(o[j], pla[t], bv[j]);
            }
        }
        // single barrier per kt (3-stage pipeline)
    }

    // Epilogue: normalize, single fp16 store
    const float inv0 = 1.0f / lrow[0];
    const float inv1 = 1.0f / lrow[1];
    const int row0 = b * 2048 + qt * 128 + wq + gr;
    #pragma unroll
    for (int j = 0; j < 8; j++) {
        const int col = h * 64 + j * 8 + 2 * gc;
        *(uint32_t*)(yh + (size_t)row0 * 1024 + col) =
            pack2h(o[j][0] * inv0, o[j][1] * inv0);
        *(uint32_t*)(yh + (size_t)(row0 + 8) * 1024 + col) =
            pack2h(o[j][2] * inv1, o[j][3] * inv1);
    }
}

// ---------------------------------------------------------------------------
// Launch
// ---------------------------------------------------------------------------
extern "C" void kernel_launch(void* const* d_in, const int* in_sizes, int n_in,
                              void* d_out, int out_size)
{
    const float* x      = (const float*)d_in[0];   // [2,2048,1024]
    const float* w_attn = (const float*)d_in[1];   // [1024,3072]
    const float* b_attn = (const float*)d_in[2];   // [3072]
    const float* w_proj = (const float*)d_in[3];   // [1024,1024]
    const float* b_proj = (const float*)d_in[4];   // [1024]
    float* out = (float*)d_out;                    // [2,2048,1024]

    __half *qkvh, *qkvl, *xh, *xl, *wa, *wp, *yh;
    cudaGetSymbolAddress((void**)&qkvh, g_qkvh);
    cudaGetSymbolAddress((void**)&qkvl, g_qkvl);
    cudaGetSymbolAddress((void**)&xh,  g_xh);
    cudaGetSymbolAddress((void**)&xl,  g_xl);
    cudaGetSymbolAddress((void**)&wa,  g_wa);
    cudaGetSymbolAddress((void**)&wp,  g_wp);
    cudaGetSymbolAddress((void**)&yh,  g_yh);

    cudaFuncSetAttribute(mma_gemm_kernel,
                         cudaFuncAttributeMaxDynamicSharedMemorySize, 92160);
    cudaFuncSetAttribute(attn_mma_kernel,
                         cudaFuncAttributeMaxDynamicSharedMemorySize, 92160);

    // Pre-pass: split x (fp16 hi/lo), transpose weights to single fp16
    split_fp16_kernel<<<4096, 256>>>(x, xh, xl, 4096 * 1024 / 4);
    transpose_fp16_kernel<<<dim3(3072 / 32, 1024 / 32), dim3(32, 8)>>>(
        w_attn, wa, 1024, 3072);
    transpose_fp16_kernel<<<dim3(1024 / 32, 1024 / 32), dim3(32, 8)>>>(
        w_proj, wp, 1024, 1024);

    // 1) qkv = x @ w_attn + b_attn  (fp16 2-product) -> fp16 hi (+lo for Q cols)
    mma_gemm_kernel<<<dim3(4096 / 128, 3072 / 128), 256, 92160>>>(
        xh, xl, wa, b_attn, nullptr, qkvh, qkvl, 1024, 4096, 3072, 1024);

    // 2) causal attention (fp16 2-product) -> yh single fp16
    attn_mma_kernel<<<dim3(2048 / 128, 16, 2), 256, 92160>>>(qkvh, qkvl, yh);

    // 3) out = y @ w_proj + b_proj  (fp16 single product, fp32 out)
    mma_gemm_kernel<<<dim3(4096 / 128, 1024 / 128), 256, 92160>>>(
        yh, nullptr, wp, b_proj, out, nullptr, nullptr, 0, 4096, 1024, 1024);
}

// round 17
// speedup vs baseline: 2.2073x; 1.3004x over previous
#include <cuda_runtime.h>
#include <cuda_fp16.h>
#include <cstdint>
#include <math.h>

// Problem constants: B=2, T=2048, C=1024, H=16, D=64, M = B*T = 4096

// ---------------------------------------------------------------------------
// Scratch (allocation forbidden -> device globals) — all single fp16 planes
// ---------------------------------------------------------------------------
__device__ __half g_qkv[4096 * 3072];             // qkv fp16
__device__ __half g_x[4096 * 1024];               // x fp16
__device__ __half g_wa[3072 * 1024];              // w_attn^T fp16  [N,K]
__device__ __half g_wp[1024 * 1024];              // w_proj^T fp16  [N,K]
__device__ __half g_y[4096 * 1024];               // attention out fp16

// ---------------------------------------------------------------------------
// PTX helpers (plain sm_100-safe: mma.sync + cp.async + ldmatrix)
// ---------------------------------------------------------------------------
__device__ __forceinline__ uint32_t smem_to_u32(const void* p) {
    uint32_t a;
    asm("{ .reg .u64 t; cvta.to.shared.u64 t, %1; cvt.u32.u64 %0, t; }" : "=r"(a) : "l"(p));
    return a;
}

#define CP_ASYNC16(dst_u32, src_ptr) \
    asm volatile("cp.async.cg.shared.global [%0], [%1], 16;" \
                 :: "r"(dst_u32), "l"(src_ptr) : "memory")
#define CP_COMMIT() asm volatile("cp.async.commit_group;" ::: "memory")
#define CP_WAIT1()  asm volatile("cp.async.wait_group 1;" ::: "memory")
#define CP_WAIT0()  asm volatile("cp.async.wait_group 0;" ::: "memory")

#define LDSM_X4(r0, r1, r2, r3, addr) \
    asm volatile("ldmatrix.sync.aligned.m8n8.x4.shared.b16 {%0,%1,%2,%3}, [%4];" \
                 : "=r"(r0), "=r"(r1), "=r"(r2), "=r"(r3) : "r"(addr))

#define LDSM_X4_TRANS(r0, r1, r2, r3, addr) \
    asm volatile("ldmatrix.sync.aligned.m8n8.x4.trans.shared.b16 {%0,%1,%2,%3}, [%4];" \
                 : "=r"(r0), "=r"(r1), "=r"(r2), "=r"(r3) : "r"(addr))

#define MMA_FP16(c, a, b) \
    asm volatile("mma.sync.aligned.m16n8k16.row.col.f32.f16.f16.f32 " \
                 "{%0,%1,%2,%3}, {%4,%5,%6,%7}, {%8,%9}, {%0,%1,%2,%3};" \
                 : "+f"((c)[0]), "+f"((c)[1]), "+f"((c)[2]), "+f"((c)[3]) \
                 : "r"((a)[0]), "r"((a)[1]), "r"((a)[2]), "r"((a)[3]), \
                   "r"((b)[0]), "r"((b)[1]))

// fp32 pair -> (hi, lo) fp16x2 packed in u32
__device__ __forceinline__ void split2h(float x, float y, uint32_t& h, uint32_t& l) {
    __half2 h2 = __floats2half2_rn(x, y);
    __half2 l2 = __floats2half2_rn(x - __half2float(__low2half(h2)),
                                   y - __half2float(__high2half(h2)));
    h = *(uint32_t*)&h2;
    l = *(uint32_t*)&l2;
}
__device__ __forceinline__ uint32_t pack2h(float x, float y) {
    __half2 h2 = __floats2half2_rn(x, y);
    return *(uint32_t*)&h2;
}

// ---------------------------------------------------------------------------
// Pre-pass 1: elementwise fp32 -> fp16 convert
// ---------------------------------------------------------------------------
__global__ __launch_bounds__(256) void convert_fp16_kernel(
    const float* __restrict__ in, __half* __restrict__ out, int n4)
{
    int i = blockIdx.x * 256 + threadIdx.x;
    if (i >= n4) return;
    float4 v = ((const float4*)in)[i];
    ((uint32_t*)out)[i * 2 + 0] = pack2h(v.x, v.y);
    ((uint32_t*)out)[i * 2 + 1] = pack2h(v.z, v.w);
}

// ---------------------------------------------------------------------------
// Pre-pass 2: W[K,N] fp32 -> W^T[N,K] fp16. 32x32 tiles.
// ---------------------------------------------------------------------------
__global__ __launch_bounds__(256) void transpose_fp16_kernel(
    const float* __restrict__ W, __half* __restrict__ Th, int K, int N)
{
    __shared__ float tile[32][33];
    const int n0 = blockIdx.x * 32;
    const int k0 = blockIdx.y * 32;
    const int tx = threadIdx.x, ty = threadIdx.y;
    #pragma unroll
    for (int j = 0; j < 4; j++) {
        int r = ty + j * 8;
        tile[r][tx] = W[(size_t)(k0 + r) * N + n0 + tx];
    }
    __syncthreads();
    #pragma unroll
    for (int j = 0; j < 4; j++) {
        int r = ty + j * 8;
        Th[(size_t)(n0 + r) * K + k0 + tx] = __float2half_rn(tile[tx][r]);
    }
}

// ---------------------------------------------------------------------------
// Tensor-core GEMM, fp16 single-product: C = A @ W^T + bias
// 8 warps, 32x64 warp tiles, CTA 128x128, K-chunk 32, 3-stage cp.async.
// smem: 3 stages x 2 tiles x 128x40 fp16 = 61440 B.
// ---------------------------------------------------------------------------
#define PITCH 40
#define TILE_H (128 * PITCH)
#define STG_H  (2 * TILE_H)

__global__ __launch_bounds__(256) void mma_gemm_kernel(
    const __half* __restrict__ A, const __half* __restrict__ W,
    const float* __restrict__ bias, float* __restrict__ Cf,
    __half* __restrict__ Ch,
    int M, int N, int K)
{
    extern __shared__ __align__(16) __half sm[];
    const uint32_t sbase = smem_to_u32(sm);
    const int tid = threadIdx.x;
    const int wid = tid >> 5, lane = tid & 31;
    const int wm = wid & 3;
    const int wn = wid >> 2;
    const int ra = lane >> 2;
    const int c2 = (lane & 3) * 2;
    const int m0 = blockIdx.x * 128;
    const int n0 = blockIdx.y * 128;

    const int r8 = lane & 7;
    const int s0 = (lane >> 3) & 1;
    const int s1 = (lane >> 4) & 1;
    const int rA = r8 + s0 * 8, kA = s1 * 8;
    const int rB = r8 + s1 * 8, kB = s0 * 8;

    const __half* srcA = A + (size_t)m0 * K;
    const __half* srcW = W + (size_t)n0 * K;

    float acc[2][8][4];
    #pragma unroll
    for (int mi = 0; mi < 2; mi++)
        #pragma unroll
        for (int ni = 0; ni < 8; ni++)
            #pragma unroll
            for (int q = 0; q < 4; q++) acc[mi][ni][q] = 0.f;

    const int NCH = K >> 5;

    auto issue_chunk = [&](int ch, int stg) {
        const int k0 = ch * 32;
        const uint32_t sb = sbase + stg * STG_H * 2;
        #pragma unroll
        for (int i = 0; i < 2; i++) {
            int idx = tid + i * 256;
            int row = idx >> 2, seg = idx & 3;
            const uint32_t d = (row * PITCH + seg * 8) * 2;
            const size_t go = (size_t)row * K + k0 + seg * 8;
            CP_ASYNC16(sb + d, srcA + go);
            CP_ASYNC16(sb + TILE_H * 2 + d, srcW + go);
        }
    };

    issue_chunk(0, 0);
    CP_COMMIT();
    issue_chunk(1, 1);
    CP_COMMIT();

    for (int ch = 0; ch < NCH; ch++) {
        const int stg = ch % 3;
        if (ch + 1 < NCH) CP_WAIT1(); else CP_WAIT0();
        __syncthreads();
        if (ch + 2 < NCH) {
            issue_chunk(ch + 2, (ch + 2) % 3);
            CP_COMMIT();
        }

        const uint32_t boff = sbase + stg * STG_H * 2;
        #pragma unroll
        for (int ks = 0; ks < 2; ks++) {
            uint32_t ah[2][4], bw[8][2];
            #pragma unroll
            for (int mi = 0; mi < 2; mi++) {
                const int row = wm * 32 + mi * 16 + rA;
                LDSM_X4(ah[mi][0], ah[mi][1], ah[mi][2], ah[mi][3],
                        boff + (row * PITCH + ks * 16 + kA) * 2);
            }
            #pragma unroll
            for (int np = 0; np < 4; np++) {
                const int row = wn * 64 + np * 16 + rB;
                LDSM_X4(bw[2 * np][0], bw[2 * np][1],
                        bw[2 * np + 1][0], bw[2 * np + 1][1],
                        boff + TILE_H * 2 + (row * PITCH + ks * 16 + kB) * 2);
            }
            #pragma unroll
            for (int mi = 0; mi < 2; mi++)
                #pragma unroll
                for (int ni = 0; ni < 8; ni++)
                    MMA_FP16(acc[mi][ni], ah[mi], bw[ni]);
        }
    }

    // Epilogue
    #pragma unroll
    for (int ni = 0; ni < 8; ni++) {
        const int col = n0 + wn * 64 + ni * 8 + c2;
        const float bv0 = bias[col], bv1 = bias[col + 1];
        #pragma unroll
        for (int mi = 0; mi < 2; mi++) {
            const int r0 = m0 + wm * 32 + mi * 16 + ra;
            const float v00 = acc[mi][ni][0] + bv0, v01 = acc[mi][ni][1] + bv1;
            const float v10 = acc[mi][ni][2] + bv0, v11 = acc[mi][ni][3] + bv1;
            if (Ch) {
                *(uint32_t*)(Ch + (size_t)r0 * N + col) = pack2h(v00, v01);
                *(uint32_t*)(Ch + (size_t)(r0 + 8) * N + col) = pack2h(v10, v11);
            } else {
                *(float2*)(Cf + (size_t)r0 * N + col) = make_float2(v00, v01);
                *(float2*)(Cf + (size_t)(r0 + 8) * N + col) = make_float2(v10, v11);
            }
        }
    }
}

// ---------------------------------------------------------------------------
// Tensor-core causal flash attention:
//   S = Q @ K^T       (single product, all fp16)
//   O += (Ph+Pl) @ V  (P hi/lo 2-product, V single fp16)
// 8 warps x 16 q-rows, CTA 128 x 64-keys, 3-stage cp.async KV pipeline.
// smem (fp16, pitch 72): Q[128] @ 0;
//   KV stages @ 9216 + stg*9216: K[64] @ +0, V[64] @ +4608.
// Total 36864 halfs = 73728 B -> 2 CTAs/SM.
// ---------------------------------------------------------------------------
#define AP 72
#define AQ 0
#define AKV0 9216
#define AKVSTRIDE 9216
#define AKH 0
#define AVH 4608

__global__ __launch_bounds__(256) void attn_mma_kernel(
    const __half* __restrict__ qkv, __half* __restrict__ y)
{
    extern __shared__ __align__(16) __half sma[];
    const uint32_t sbase = smem_to_u32(sma);
    const int tid = threadIdx.x;
    const int wid = tid >> 5, lane = tid & 31;
    const int gr = lane >> 2;
    const int gc = lane & 3;
    const int qt = gridDim.x - 1 - blockIdx.x;    // heavy CTAs first
    const int h  = blockIdx.y;
    const int b  = blockIdx.z;
    const int wq = wid * 16;

    const int r8 = lane & 7;
    const int s0 = (lane >> 3) & 1;
    const int s1 = (lane >> 4) & 1;
    const int rA = r8 + s0 * 8, kA = s1 * 8;
    const int rB = r8 + s1 * 8, kB = s0 * 8;

    const float SSCALE = 0.125f * 1.44269504088896f;  // 1/sqrt(64)*log2(e)

    const size_t kcol = (size_t)(b * 2048) * 3072 + 1024 + h * 64;
    const size_t vcol = kcol + 1024;

    auto issue_kv = [&](int kt, int stg) {
        const uint32_t bb = sbase + (AKV0 + stg * AKVSTRIDE) * 2;
        #pragma unroll
        for (int i = 0; i < 2; i++) {
            int f = tid + i * 256;                // 0..511
            int j = f >> 3, seg = f & 7;
            const size_t off = (size_t)(kt * 64 + j) * 3072 + seg * 8;
            const uint32_t d = (j * AP + seg * 8) * 2;
            CP_ASYNC16(bb + AKH * 2 + d, qkv + kcol + off);
            CP_ASYNC16(bb + AVH * 2 + d, qkv + vcol + off);
        }
    };

    // Load Q tile (128 x 64 fp16)
    {
        const size_t qrow = (size_t)(b * 2048 + qt * 128) * 3072 + h * 64;
        #pragma unroll
        for (int i = 0; i < 4; i++) {
            int f = tid + i * 256;                // 0..1023
            int r = f >> 3, seg = f & 7;
            *(uint4*)&sma[AQ + r * AP + seg * 8] =
                *(const uint4*)(qkv + qrow + (size_t)r * 3072 + seg * 8);
        }
    }

    float o[8][4];
    #pragma unroll
    for (int j = 0; j < 8; j++)
        #pragma unroll
        for (int q = 0; q < 4; q++) o[j][q] = 0.f;
    float mrow[2] = {-1e30f, -1e30f};
    float lrow[2] = {0.f, 0.f};

    const int kt_max = 2 * qt + 1;

    issue_kv(0, 0);
    CP_COMMIT();
    if (kt_max >= 1) {
        issue_kv(1, 1);
        CP_COMMIT();
    }

    for (int kt = 0; kt <= kt_max; kt++) {
        const int stg = kt % 3;
        if (kt < kt_max) CP_WAIT1(); else CP_WAIT0();
        __syncthreads();
        if (kt + 2 <= kt_max) {
            issue_kv(kt + 2, (kt + 2) % 3);
            CP_COMMIT();
        }

        const uint32_t kvb = sbase + (AKV0 + stg * AKVSTRIDE) * 2;

        // S = Q K^T (16x64 per warp), single product
        float s[8][4];
        #pragma unroll
        for (int j = 0; j < 8; j++)
            #pragma unroll
            for (int q = 0; q < 4; q++) s[j][q] = 0.f;

        #pragma unroll
        for (int ks = 0; ks < 4; ks++) {
            uint32_t aq[4], bk[8][2];
            LDSM_X4(aq[0], aq[1], aq[2], aq[3],
                    sbase + (AQ + (wq + rA) * AP + ks * 16 + kA) * 2);
            #pragma unroll
            for (int np = 0; np < 4; np++) {
                LDSM_X4(bk[2 * np][0], bk[2 * np][1],
                        bk[2 * np + 1][0], bk[2 * np + 1][1],
                        kvb + AKH * 2 + ((np * 16 + rB) * AP + ks * 16 + kB) * 2);
            }
            #pragma unroll
            for (int j = 0; j < 8; j++)
                MMA_FP16(s[j], aq, bk[j]);
        }

        // Scale + causal mask
        #pragma unroll
        for (int j = 0; j < 8; j++)
            #pragma unroll
            for (int q = 0; q < 4; q++) s[j][q] *= SSCALE;

        if (kt >= 2 * qt) {
            const int row0 = qt * 128 + wq + gr;
            #pragma unroll
            for (int j = 0; j < 8; j++) {
                const int col = kt * 64 + j * 8 + 2 * gc;
                if (col > row0)         s[j][0] = -1e30f;
                if (col + 1 > row0)     s[j][1] = -1e30f;
                if (col > row0 + 8)     s[j][2] = -1e30f;
                if (col + 1 > row0 + 8) s[j][3] = -1e30f;
            }
        }

        // Online softmax
        #pragma unroll
        for (int i = 0; i < 2; i++) {
            const int q0i = i * 2;
            float mx = -1e30f;
            #pragma unroll
            for (int j = 0; j < 8; j++)
                mx = fmaxf(mx, fmaxf(s[j][q0i], s[j][q0i + 1]));
            mx = fmaxf(mx, __shfl_xor_sync(0xffffffffu, mx, 1));
            mx = fmaxf(mx, __shfl_xor_sync(0xffffffffu, mx, 2));
            const float mnew = fmaxf(mrow[i], mx);
            const float alpha = exp2f(mrow[i] - mnew);
            float rsum = 0.f;
            #pragma unroll
            for (int j = 0; j < 8; j++) {
                s[j][q0i]     = exp2f(s[j][q0i] - mnew);
                s[j][q0i + 1] = exp2f(s[j][q0i + 1] - mnew);
                rsum += s[j][q0i] + s[j][q0i + 1];
            }
            rsum += __shfl_xor_sync(0xffffffffu, rsum, 1);
            rsum += __shfl_xor_sync(0xffffffffu, rsum, 2);
            lrow[i] = lrow[i] * alpha + rsum;
            mrow[i] = mnew;
            #pragma unroll
            for (int j = 0; j < 8; j++) {
                o[j][q0i]     *= alpha;
                o[j][q0i + 1] *= alpha;
            }
        }

        // Pack P hi/lo fp16 A-fragments
        uint32_t pha[4][4], pla[4][4];
        #pragma unroll
        for (int t = 0; t < 4; t++) {
            split2h(s[2 * t][0],     s[2 * t][1],     pha[t][0], pla[t][0]);
            split2h(s[2 * t][2],     s[2 * t][3],     pha[t][1], pla[t][1]);
            split2h(s[2 * t + 1][0], s[2 * t + 1][1], pha[t][2], pla[t][2]);
            split2h(s[2 * t + 1][2], s[2 * t + 1][3], pha[t][3], pla[t][3]);
        }

        // O += P V (V natural in smem; ldmatrix.trans B-frags)
        #pragma unroll
        for (int t = 0; t < 4; t++) {
            uint32_t bv[8][2];
            #pragma unroll
            for (int np = 0; np < 4; np++) {
                LDSM_X4_TRANS(bv[2 * np][0], bv[2 * np][1],
                              bv[2 * np + 1][0], bv[2 * np + 1][1],
                              kvb + AVH * 2 + ((t * 16 + rA) * AP + np * 16 + kA) * 2);
            }
            #pragma unroll
            for (int j = 0; j < 8; j++) {
                MMA_FP16(o[j], pha[t], bv[j]);
                MMA_FP16(o[j], pla[t], bv[j]);
            }
        }
    }

    // Epilogue: normalize, single fp16 store
    const float inv0 = 1.0f / lrow[0];
    const float inv1 = 1.0f / lrow[1];
    const int row0 = b * 2048 + qt * 128 + wq + gr;
    #pragma unroll
    for (int j = 0; j < 8; j++) {
        const int col = h * 64 + j * 8 + 2 * gc;
        *(uint32_t*)(y + (size_t)row0 * 1024 + col) =
            pack2h(o[j][0] * inv0, o[j][1] * inv0);
        *(uint32_t*)(y + (size_t)(row0 + 8) * 1024 + col) =
            pack2h(o[j][2] * inv1, o[j][3] * inv1);
    }
}

// ---------------------------------------------------------------------------
// Launch
// ---------------------------------------------------------------------------
extern "C" void kernel_launch(void* const* d_in, const int* in_sizes, int n_in,
                              void* d_out, int out_size)
{
    const float* x      = (const float*)d_in[0];   // [2,2048,1024]
    const float* w_attn = (const float*)d_in[1];   // [1024,3072]
    const float* b_attn = (const float*)d_in[2];   // [3072]
    const float* w_proj = (const float*)d_in[3];   // [1024,1024]
    const float* b_proj = (const float*)d_in[4];   // [1024]
    float* out = (float*)d_out;                    // [2,2048,1024]

    __half *qkv, *xh, *wa, *wp, *y;
    cudaGetSymbolAddress((void**)&qkv, g_qkv);
    cudaGetSymbolAddress((void**)&xh,  g_x);
    cudaGetSymbolAddress((void**)&wa,  g_wa);
    cudaGetSymbolAddress((void**)&wp,  g_wp);
    cudaGetSymbolAddress((void**)&y,   g_y);

    cudaFuncSetAttribute(mma_gemm_kernel,
                         cudaFuncAttributeMaxDynamicSharedMemorySize, 61440);
    cudaFuncSetAttribute(attn_mma_kernel,
                         cudaFuncAttributeMaxDynamicSharedMemorySize, 73728);

    // Pre-pass: convert x to fp16, transpose weights to fp16
    convert_fp16_kernel<<<4096, 256>>>(x, xh, 4096 * 1024 / 4);
    transpose_fp16_kernel<<<dim3(3072 / 32, 1024 / 32), dim3(32, 8)>>>(
        w_attn, wa, 1024, 3072);
    transpose_fp16_kernel<<<dim3(1024 / 32, 1024 / 32), dim3(32, 8)>>>(
        w_proj, wp, 1024, 1024);

    // 1) qkv = x @ w_attn + b_attn  (single product) -> fp16
    mma_gemm_kernel<<<dim3(4096 / 128, 3072 / 128), 256, 61440>>>(
        xh, wa, b_attn, nullptr, qkv, 4096, 3072, 1024);

    // 2) causal attention -> y fp16
    attn_mma_kernel<<<dim3(2048 / 128, 16, 2), 256, 73728>>>(qkv, y);

    // 3) out = y @ w_proj + b_proj  (single product, fp32 out)
    mma_gemm_kernel<<<dim3(4096 / 128, 1024 / 128), 256, 61440>>>(
        y, wp, b_proj, out, nullptr, 4096, 1024, 1024);
}